// round 1
// baseline (speedup 1.0000x reference)
#include <cuda_runtime.h>
#include <math.h>

// Problem constants
#define Bq   256
#define Lq   128
#define INDq 6
#define Dq   256
#define Hq   8
#define DKq  32
#define NLq  6
#define Eq   8
#define FFq  1024
#define NMOEq 3
#define NHq  5
#define NT   (Bq*Lq)      // 32768 tokens
#define NP   (2*NT)       // 65536 token-expert pairs

// ---------------- scratch (device globals; no allocation allowed) ----------
__device__ float g_h  [NT*Dq];
__device__ float g_q  [NT*Dq];
__device__ float g_k  [NT*Dq];
__device__ float g_v  [NT*Dq];
__device__ float g_att[NT*Dq];
__device__ float g_H  [NP*FFq];     // 256 MB expert-hidden scratch (pair-indexed)
__device__ float g_Y  [NP*Dq];      // 64 MB expert-output scratch
__device__ int   g_cnt [NMOEq*Eq];
__device__ int   g_tok [NMOEq*Eq*NT];
__device__ int   g_pair[NMOEq*Eq*NT];
__device__ float g_pw  [NMOEq*NP];
__device__ int   g_pe  [NMOEq*NP];

// ---------------- small kernels -------------------------------------------
__global__ void zero_cnt_kernel() {
    if (threadIdx.x < NMOEq*Eq) g_cnt[threadIdx.x] = 0;
}

__global__ void embed_kernel(const float* __restrict__ x,
                             const float* __restrict__ w,
                             const float* __restrict__ b) {
    int t = blockIdx.x, d = threadIdx.x;
    float acc = b[d];
#pragma unroll
    for (int k = 0; k < INDq; k++) acc += x[t*INDq + k] * w[k*Dq + d];
    g_h[(size_t)t*Dq + d] = acc;
}

// ---------------- generic 128x128 fp32 GEMM with gather/scatter ------------
// C[cidx[m]][n] (epi) = A[aidx[m]][:] dot B[:, n]
// epi: 0 = plain store, 1 = residual add (C += acc), 2 = gelu(acc + bias)
__global__ __launch_bounds__(256)
void gemm128(const float* __restrict__ A,
             const float* __restrict__ Bbase,
             float* __restrict__ C,
             const float* __restrict__ biasbase,
             int M, int Nn, int K, int ldc,
             const int* __restrict__ cntp,
             const int* __restrict__ aidxb,
             const int* __restrict__ cidxb,
             int zBstride, int zbstride, int idxcap, int epi)
{
    int e = blockIdx.z;
    int Mloc = cntp ? cntp[e] : M;
    int m0 = blockIdx.x << 7;
    if (m0 >= Mloc) return;
    int n0 = blockIdx.y << 7;
    const float* Bp = Bbase + (size_t)e * zBstride;
    const int* al = aidxb ? aidxb + (size_t)e * idxcap : nullptr;
    const int* cl = cidxb ? cidxb + (size_t)e * idxcap : nullptr;

    __shared__ float As[16*132];   // A^T tile, padded
    __shared__ float Bs[16*128];

    int tid = threadIdx.x;
    int tn = tid & 15, tm = tid >> 4;

    float acc[8][8];
#pragma unroll
    for (int i = 0; i < 8; i++)
#pragma unroll
        for (int j = 0; j < 8; j++) acc[i][j] = 0.f;

    for (int kt = 0; kt < K; kt += 16) {
        // Load A tile (128 rows x 16 k), transposed into As
#pragma unroll
        for (int it = 0; it < 2; it++) {
            int idx = tid + (it << 8);
            int row = idx >> 2;
            int kq  = (idx & 3) << 2;
            float4 av = make_float4(0.f, 0.f, 0.f, 0.f);
            int gm = m0 + row;
            if (gm < Mloc) {
                int ar = al ? al[gm] : gm;
                av = *reinterpret_cast<const float4*>(A + (size_t)ar*K + kt + kq);
            }
            As[(kq+0)*132 + row] = av.x;
            As[(kq+1)*132 + row] = av.y;
            As[(kq+2)*132 + row] = av.z;
            As[(kq+3)*132 + row] = av.w;
        }
        // Load B tile (16 k x 128 n)
#pragma unroll
        for (int it = 0; it < 2; it++) {
            int idx = tid + (it << 8);
            int rb = idx >> 5;
            int nq = (idx & 31) << 2;
            float4 bv = *reinterpret_cast<const float4*>(Bp + (size_t)(kt + rb)*Nn + n0 + nq);
            *reinterpret_cast<float4*>(&Bs[rb*128 + nq]) = bv;
        }
        __syncthreads();
#pragma unroll
        for (int kk = 0; kk < 16; kk++) {
            float4 t0 = *reinterpret_cast<float4*>(&As[kk*132 + tm*8]);
            float4 t1 = *reinterpret_cast<float4*>(&As[kk*132 + tm*8 + 4]);
            float4 u0 = *reinterpret_cast<float4*>(&Bs[kk*128 + tn*8]);
            float4 u1 = *reinterpret_cast<float4*>(&Bs[kk*128 + tn*8 + 4]);
            float a[8] = {t0.x,t0.y,t0.z,t0.w,t1.x,t1.y,t1.z,t1.w};
            float b[8] = {u0.x,u0.y,u0.z,u0.w,u1.x,u1.y,u1.z,u1.w};
#pragma unroll
            for (int i = 0; i < 8; i++)
#pragma unroll
                for (int j = 0; j < 8; j++)
                    acc[i][j] += a[i] * b[j];
        }
        __syncthreads();
    }

    // Epilogue
#pragma unroll
    for (int i = 0; i < 8; i++) {
        int gm = m0 + tm*8 + i;
        if (gm >= Mloc) continue;
        int cr = cl ? cl[gm] : gm;
        float* cp = C + (size_t)cr*ldc + n0 + tn*8;
        if (epi == 0) {
            float4 v0 = make_float4(acc[i][0], acc[i][1], acc[i][2], acc[i][3]);
            float4 v1 = make_float4(acc[i][4], acc[i][5], acc[i][6], acc[i][7]);
            *reinterpret_cast<float4*>(cp)     = v0;
            *reinterpret_cast<float4*>(cp + 4) = v1;
        } else if (epi == 1) {
            float4 o0 = *reinterpret_cast<float4*>(cp);
            float4 o1 = *reinterpret_cast<float4*>(cp + 4);
            o0.x += acc[i][0]; o0.y += acc[i][1]; o0.z += acc[i][2]; o0.w += acc[i][3];
            o1.x += acc[i][4]; o1.y += acc[i][5]; o1.z += acc[i][6]; o1.w += acc[i][7];
            *reinterpret_cast<float4*>(cp)     = o0;
            *reinterpret_cast<float4*>(cp + 4) = o1;
        } else {
            const float* bi = biasbase + (size_t)e*zbstride + n0 + tn*8;
            float vals[8];
#pragma unroll
            for (int j = 0; j < 8; j++) {
                float vx = acc[i][j] + bi[j];
                vals[j] = 0.5f * vx * (1.0f + erff(vx * 0.70710678118654752f));
            }
            float4 v0 = make_float4(vals[0], vals[1], vals[2], vals[3]);
            float4 v1 = make_float4(vals[4], vals[5], vals[6], vals[7]);
            *reinterpret_cast<float4*>(cp)     = v0;
            *reinterpret_cast<float4*>(cp + 4) = v1;
        }
    }
}

// ---------------- attention (one block per (batch, head)) ------------------
__global__ __launch_bounds__(128)
void attn_kernel(const float* __restrict__ wfreq, const float* __restrict__ wphase)
{
    int b = blockIdx.x >> 3, h = blockIdx.x & 7;
    __shared__ float ks[Lq*DKq];
    __shared__ float vs[Lq*DKq];
    __shared__ float wv[Lq];
    int tid = threadIdx.x;
    size_t base = (size_t)(b*Lq)*Dq + h*DKq;

    for (int idx = tid; idx < Lq*DKq; idx += 128) {
        int r = idx >> 5, c = idx & 31;
        size_t g = base + (size_t)r*Dq + c;
        ks[idx] = g_k[g];
        vs[idx] = g_v[g];
    }
    {
        float f = wfreq[h], ph = wphase[h];
        wv[tid] = cosf((6.2831853071795864f * f) * (float)tid + ph);
    }
    __syncthreads();

    // this thread's query row
    float qr[DKq];
    const float4* qp = reinterpret_cast<const float4*>(g_q + base + (size_t)tid*Dq);
#pragma unroll
    for (int w = 0; w < 8; w++) {
        float4 f4 = qp[w];
        qr[4*w+0] = f4.x; qr[4*w+1] = f4.y; qr[4*w+2] = f4.z; qr[4*w+3] = f4.w;
    }

    float m = -1e30f, ssum = 0.f;
    float acc[DKq];
#pragma unroll
    for (int c = 0; c < DKq; c++) acc[c] = 0.f;
    const float scale = 0.17677669529663687f;   // 1/sqrt(32)

    for (int kk = 0; kk < Lq; kk++) {
        float s = 0.f;
#pragma unroll
        for (int c = 0; c < DKq; c++) s += qr[c] * ks[kk*DKq + c];
        s = s * scale * wv[kk];
        float mn = fmaxf(m, s);
        float corr = __expf(m - mn);
        float p = __expf(s - mn);
        ssum = ssum * corr + p;
#pragma unroll
        for (int c = 0; c < DKq; c++) acc[c] = acc[c]*corr + p*vs[kk*DKq + c];
        m = mn;
    }
    float inv = 1.f / ssum;
    float* op = g_att + base + (size_t)tid*Dq;
#pragma unroll
    for (int w = 0; w < 8; w++) {
        float4 f4 = make_float4(acc[4*w]*inv, acc[4*w+1]*inv, acc[4*w+2]*inv, acc[4*w+3]*inv);
        *reinterpret_cast<float4*>(op + 4*w) = f4;
    }
}

// ---------------- MoE router (one warp per token) --------------------------
__global__ __launch_bounds__(256)
void router_kernel(const float* __restrict__ rw, const float* __restrict__ rb, int layer)
{
    int warp = threadIdx.x >> 5, lane = threadIdx.x & 31;
    int t = (blockIdx.x << 3) + warp;

    float lg[Eq];
#pragma unroll
    for (int e = 0; e < Eq; e++) lg[e] = 0.f;
    const float* hp = g_h + (size_t)t*Dq;
    for (int kk = lane; kk < Dq; kk += 32) {
        float xv = hp[kk];
#pragma unroll
        for (int e = 0; e < Eq; e++) lg[e] += xv * rw[kk*Eq + e];
    }
#pragma unroll
    for (int e = 0; e < Eq; e++)
#pragma unroll
        for (int o = 16; o; o >>= 1) lg[e] += __shfl_xor_sync(0xffffffffu, lg[e], o);

    if (lane == 0) {
        float l[Eq], p[Eq];
        float mx = -1e30f;
#pragma unroll
        for (int e = 0; e < Eq; e++) { l[e] = lg[e] + rb[e]; mx = fmaxf(mx, l[e]); }
#pragma unroll
        for (int e = 0; e < Eq; e++) p[e] = __expf(l[e] - mx);
        int i0 = 0;
#pragma unroll
        for (int e = 1; e < Eq; e++) if (p[e] > p[i0]) i0 = e;
        int i1 = -1;
#pragma unroll
        for (int e = 0; e < Eq; e++) if (e != i0 && (i1 < 0 || p[e] > p[i1])) i1 = e;
        float w0 = p[i0], w1 = p[i1];
        float s2 = w0 + w1;
        w0 /= s2; w1 /= s2;

        int* cnt   = g_cnt  + layer*Eq;
        int* tokl  = g_tok  + (size_t)layer*Eq*NT;
        int* pairl = g_pair + (size_t)layer*Eq*NT;
        float* pwp = g_pw   + (size_t)layer*NP;
        int* pep   = g_pe   + (size_t)layer*NP;

        int p0 = atomicAdd(&cnt[i0], 1);
        tokl[i0*NT + p0] = t;  pairl[i0*NT + p0] = 2*t;
        int p1 = atomicAdd(&cnt[i1], 1);
        tokl[i1*NT + p1] = t;  pairl[i1*NT + p1] = 2*t + 1;
        pwp[2*t] = w0; pwp[2*t+1] = w1;
        pep[2*t] = i0; pep[2*t+1] = i1;
    }
}

// ---------------- MoE combine: h += w0*(Y0+b2[e0]) + w1*(Y1+b2[e1]) --------
__global__ void moe_combine(const float* __restrict__ b2, int layer)
{
    int t = blockIdx.x, d = threadIdx.x;
    const float* pwp = g_pw + (size_t)layer*NP;
    const int*   pep = g_pe + (size_t)layer*NP;
    float w0 = pwp[2*t], w1 = pwp[2*t+1];
    int e0 = pep[2*t], e1 = pep[2*t+1];
    size_t i0 = (size_t)(2*t)*Dq + d;
    g_h[(size_t)t*Dq + d] += w0*(g_Y[i0]      + b2[e0*Dq + d])
                           + w1*(g_Y[i0 + Dq] + b2[e1*Dq + d]);
}

// ---------------- final LN + prediction heads (one block per batch) --------
__global__ __launch_bounds__(256)
void head_kernel(const float* __restrict__ lng, const float* __restrict__ lnb,
                 const float* __restrict__ pw,  const float* __restrict__ pb,
                 const float* __restrict__ uw,  const float* __restrict__ ub,
                 float* __restrict__ out)
{
    int b = blockIdx.x, tid = threadIdx.x;
    int warp = tid >> 5, lane = tid & 31;
    __shared__ float z[Dq];
    __shared__ float red[8];

    size_t t = (size_t)b*Lq + (Lq - 1);
    float v = g_h[t*Dq + tid];

    // mean
    float s = v;
#pragma unroll
    for (int o = 16; o; o >>= 1) s += __shfl_xor_sync(0xffffffffu, s, o);
    if (lane == 0) red[warp] = s;
    __syncthreads();
    float tot = 0.f;
#pragma unroll
    for (int i = 0; i < 8; i++) tot += red[i];
    float mean = tot * (1.f / Dq);
    __syncthreads();

    // variance
    float dv = v - mean;
    float q = dv * dv;
#pragma unroll
    for (int o = 16; o; o >>= 1) q += __shfl_xor_sync(0xffffffffu, q, o);
    if (lane == 0) red[warp] = q;
    __syncthreads();
    float vtot = 0.f;
#pragma unroll
    for (int i = 0; i < 8; i++) vtot += red[i];
    float var = vtot * (1.f / Dq);

    z[tid] = dv * rsqrtf(var + 1e-5f) * lng[tid] + lnb[tid];
    __syncthreads();

    for (int o = warp; o < 2*NHq; o += 8) {
        int j = o % NHq;
        int isu = o / NHq;
        const float* W = isu ? uw : pw;
        float p = 0.f;
        for (int d = lane; d < Dq; d += 32) p += z[d] * W[d*NHq + j];
#pragma unroll
        for (int off = 16; off; off >>= 1) p += __shfl_xor_sync(0xffffffffu, p, off);
        if (lane == 0) {
            float r = p + (isu ? ub[j] : pb[j]);
            if (isu) r = fmaxf(r, 0.f) + log1pf(__expf(-fabsf(r)));  // softplus
            out[isu*(Bq*NHq) + b*NHq + j] = r;
        }
    }
}

// ---------------- host side -----------------------------------------------
extern "C" void kernel_launch(void* const* d_in, const int* in_sizes, int n_in,
                              void* d_out, int out_size)
{
    const float* x      = (const float*)d_in[0];
    const float* embw   = (const float*)d_in[1];
    const float* embb   = (const float*)d_in[2];
    const float* qw     = (const float*)d_in[3];
    const float* kw     = (const float*)d_in[4];
    const float* vw     = (const float*)d_in[5];
    const float* ow     = (const float*)d_in[6];
    const float* wfreq  = (const float*)d_in[7];
    const float* wphase = (const float*)d_in[8];
    const float* rw     = (const float*)d_in[9];
    const float* rb     = (const float*)d_in[10];
    const float* ew1    = (const float*)d_in[11];
    const float* eb1    = (const float*)d_in[12];
    const float* ew2    = (const float*)d_in[13];
    const float* eb2    = (const float*)d_in[14];
    const float* lng    = (const float*)d_in[15];
    const float* lnb    = (const float*)d_in[16];
    const float* predw  = (const float*)d_in[17];
    const float* predb  = (const float*)d_in[18];
    const float* uncw   = (const float*)d_in[19];
    const float* uncb   = (const float*)d_in[20];
    float* out = (float*)d_out;

    float *h, *q, *k, *v, *att, *Hb, *Yb;
    int *cnt, *tok, *pair;
    cudaGetSymbolAddress((void**)&h,    g_h);
    cudaGetSymbolAddress((void**)&q,    g_q);
    cudaGetSymbolAddress((void**)&k,    g_k);
    cudaGetSymbolAddress((void**)&v,    g_v);
    cudaGetSymbolAddress((void**)&att,  g_att);
    cudaGetSymbolAddress((void**)&Hb,   g_H);
    cudaGetSymbolAddress((void**)&Yb,   g_Y);
    cudaGetSymbolAddress((void**)&cnt,  g_cnt);
    cudaGetSymbolAddress((void**)&tok,  g_tok);
    cudaGetSymbolAddress((void**)&pair, g_pair);

    zero_cnt_kernel<<<1, 32>>>();
    embed_kernel<<<NT, Dq>>>(x, embw, embb);

    dim3 gd(NT/128, Dq/128, 1);
    for (int i = 0; i < NLq; i++) {
        size_t wo = (size_t)i * Dq * Dq;
        gemm128<<<gd, 256>>>(h,   qw + wo, q, nullptr, NT, Dq, Dq, Dq,
                             nullptr, nullptr, nullptr, 0, 0, 0, 0);
        gemm128<<<gd, 256>>>(h,   kw + wo, k, nullptr, NT, Dq, Dq, Dq,
                             nullptr, nullptr, nullptr, 0, 0, 0, 0);
        gemm128<<<gd, 256>>>(h,   vw + wo, v, nullptr, NT, Dq, Dq, Dq,
                             nullptr, nullptr, nullptr, 0, 0, 0, 0);
        attn_kernel<<<Bq*Hq, 128>>>(wfreq + i*Hq, wphase + i*Hq);
        gemm128<<<gd, 256>>>(att, ow + wo, h, nullptr, NT, Dq, Dq, Dq,
                             nullptr, nullptr, nullptr, 0, 0, 0, 1);

        if ((i & 1) == 0) {
            int j = i >> 1;
            router_kernel<<<NT/8, 256>>>(rw + (size_t)j*Dq*Eq, rb + j*Eq, j);

            dim3 g1(NT/128, FFq/128, Eq);
            gemm128<<<g1, 256>>>(h, ew1 + (size_t)j*Eq*Dq*FFq, Hb,
                                 eb1 + (size_t)j*Eq*FFq,
                                 0, FFq, Dq, FFq,
                                 cnt + j*Eq,
                                 tok  + (size_t)j*Eq*NT,
                                 pair + (size_t)j*Eq*NT,
                                 Dq*FFq, FFq, NT, 2);

            dim3 g2(NT/128, Dq/128, Eq);
            gemm128<<<g2, 256>>>(Hb, ew2 + (size_t)j*Eq*FFq*Dq, Yb,
                                 nullptr,
                                 0, Dq, FFq, Dq,
                                 cnt + j*Eq,
                                 pair + (size_t)j*Eq*NT,
                                 pair + (size_t)j*Eq*NT,
                                 FFq*Dq, 0, NT, 0);

            moe_combine<<<NT, Dq>>>(eb2 + (size_t)j*Eq*Dq, j);
        }
    }

    head_kernel<<<Bq, 256>>>(lng, lnb, predw, predb, uncw, uncb, out);
}

// round 3
// speedup vs baseline: 2.3753x; 2.3753x over previous
#include <cuda_runtime.h>
#include <math.h>
#include <stdint.h>

// Problem constants
#define Bq   256
#define Lq   128
#define INDq 6
#define Dq   256
#define Hq   8
#define DKq  32
#define NLq  6
#define Eq   8
#define FFq  1024
#define NMOEq 3
#define NHq  5
#define NT   (Bq*Lq)      // 32768 tokens
#define NP   (2*NT)       // 65536 token-expert pairs

// ---------------- scratch (device globals; no allocation allowed) ----------
__device__ float g_h  [NT*Dq];
__device__ float g_q  [NT*Dq];
__device__ float g_k  [NT*Dq];
__device__ float g_v  [NT*Dq];
__device__ float g_att[NT*Dq];
__device__ float g_H  [NP*FFq];     // expert-hidden scratch (pair-indexed)
__device__ float g_Y  [NP*Dq];      // expert-output scratch
__device__ int   g_cnt [NMOEq*Eq];
__device__ int   g_tok [NMOEq*Eq*NT];
__device__ int   g_pair[NMOEq*Eq*NT];
__device__ float g_pw  [NMOEq*NP];
__device__ int   g_pe  [NMOEq*NP];
// transposed (tf32-rounded) weights: [N,K] K-major
__device__ float g_qwt[NLq*Dq*Dq];
__device__ float g_kwt[NLq*Dq*Dq];
__device__ float g_vwt[NLq*Dq*Dq];
__device__ float g_owt[NLq*Dq*Dq];
__device__ float g_w1t[NMOEq*Eq*FFq*Dq];
__device__ float g_w2t[NMOEq*Eq*Dq*FFq];

// ---------------- helpers ---------------------------------------------------
__device__ __forceinline__ float rna_tf32(float x) {
    uint32_t u;
    asm("cvt.rna.tf32.f32 %0, %1;" : "=r"(u) : "f"(x));
    return __uint_as_float(u);
}
__device__ __forceinline__ uint32_t rna_tf32_u(float x) {
    uint32_t u;
    asm("cvt.rna.tf32.f32 %0, %1;" : "=r"(u) : "f"(x));
    return u;
}
__device__ __forceinline__ uint32_t smem_u32(const void* p) {
    uint32_t a;
    asm("{ .reg .u64 t; cvta.to.shared.u64 t, %1; cvt.u32.u64 %0, t; }" : "=r"(a) : "l"(p));
    return a;
}
__device__ __forceinline__ void cp16(uint32_t saddr, const void* g, int sz) {
    asm volatile("cp.async.ca.shared.global [%0], [%1], 16, %2;"
                 :: "r"(saddr), "l"(g), "r"(sz) : "memory");
}
#define CP_COMMIT()  asm volatile("cp.async.commit_group;" ::: "memory")
#define CP_WAIT1()   asm volatile("cp.async.wait_group 1;" ::: "memory")

#define MMA_TF32(d, a, b) \
    asm volatile("mma.sync.aligned.m16n8k8.row.col.f32.tf32.tf32.f32 " \
                 "{%0,%1,%2,%3}, {%4,%5,%6,%7}, {%8,%9}, {%0,%1,%2,%3};" \
                 : "+f"((d)[0]), "+f"((d)[1]), "+f"((d)[2]), "+f"((d)[3]) \
                 : "r"((a)[0]), "r"((a)[1]), "r"((a)[2]), "r"((a)[3]), \
                   "r"((b)[0]), "r"((b)[1]))

// ---------------- small kernels -------------------------------------------
__global__ void zero_cnt_kernel() {
    if (threadIdx.x < NMOEq*Eq) g_cnt[threadIdx.x] = 0;
}

__global__ void embed_kernel(const float* __restrict__ x,
                             const float* __restrict__ w,
                             const float* __restrict__ b) {
    int t = blockIdx.x, d = threadIdx.x;
    float acc = b[d];
#pragma unroll
    for (int k = 0; k < INDq; k++) acc += x[t*INDq + k] * w[k*Dq + d];
    g_h[(size_t)t*Dq + d] = acc;
}

// Batched transpose with tf32 rounding: out[z][c][r] = rna(in[z][r][c])
__global__ void transpose_rna(const float* __restrict__ in, float* __restrict__ out,
                              int R, int C) {
    __shared__ float t[32][33];
    const float* ip = in  + (size_t)blockIdx.z * R * C;
    float*       op = out + (size_t)blockIdx.z * R * C;
    int c0 = blockIdx.x * 32, r0 = blockIdx.y * 32;
    int tx = threadIdx.x, ty = threadIdx.y;
#pragma unroll
    for (int j = 0; j < 32; j += 8)
        t[ty + j][tx] = ip[(size_t)(r0 + ty + j) * C + c0 + tx];
    __syncthreads();
#pragma unroll
    for (int j = 0; j < 32; j += 8)
        op[(size_t)(c0 + ty + j) * R + r0 + tx] = rna_tf32(t[tx][ty + j]);
}

// ---------------- TF32 warp-MMA GEMM (128x128 tile, BK=32) -----------------
// C[cidx[m]][:] (epi) = A[aidx[m]][:K] dot Bt[n][:K]   (Bt is [N,K] K-major)
// epi: 0 = store, 1 = residual add, 2 = gelu(acc + bias)
#define ASZ (128*36)                 // floats per tile buffer (row stride 36)
#define SMEM_FLOATS (4*ASZ)          // A0 A1 B0 B1
#define SMEM_BYTES  (SMEM_FLOATS*4)  // 73728

__global__ __launch_bounds__(256)
void tc_gemm(const float* __restrict__ A,
             const float* __restrict__ Btbase,
             float* __restrict__ C,
             const float* __restrict__ biasbase,
             int M, int K, int ldc,
             const int* __restrict__ cntp,
             const int* __restrict__ aidxb,
             const int* __restrict__ cidxb,
             int zBstride, int zbstride, int idxcap, int epi)
{
    extern __shared__ float sm[];
    int e = blockIdx.z;
    int Mloc = cntp ? cntp[e] : M;
    int m0 = blockIdx.x << 7;
    if (m0 >= Mloc) return;
    int n0 = blockIdx.y << 7;
    const float* Bp = Btbase + (size_t)e * zBstride;
    const int* al = aidxb ? aidxb + (size_t)e * idxcap : nullptr;
    const int* cl = cidxb ? cidxb + (size_t)e * idxcap : nullptr;

    int tid = threadIdx.x, wid = tid >> 5, lane = tid & 31;
    int warp_m = wid & 1, warp_n = wid >> 1;
    uint32_t su = smem_u32(sm);

    // load-duty geometry: thread handles float4 #(tid + i*256), i=0..3
    int c4 = tid & 7;                 // float4-column within 32-float row
    int srow0 = tid >> 3;             // smem row for i=0; +32 per i

    int rowA[4], szA[4];
#pragma unroll
    for (int i = 0; i < 4; i++) {
        int r = srow0 + 32*i;
        int gm = m0 + r;
        bool v = gm < Mloc;
        rowA[i] = v ? (al ? al[gm] : gm) : 0;
        szA[i] = v ? 16 : 0;
    }

    float d[4][4][4];
#pragma unroll
    for (int i = 0; i < 4; i++)
#pragma unroll
        for (int j = 0; j < 4; j++)
#pragma unroll
            for (int u = 0; u < 4; u++) d[i][j][u] = 0.f;

#define ISSUE(chunk, p) do { \
    int kt = (chunk) << 5; \
    _Pragma("unroll") \
    for (int i = 0; i < 4; i++) { \
        int r = srow0 + 32*i; \
        cp16(su + 4*((p)*ASZ + r*36 + c4*4), \
             A + (size_t)rowA[i]*K + kt + c4*4, szA[i]); \
    } \
    _Pragma("unroll") \
    for (int i = 0; i < 4; i++) { \
        int r = srow0 + 32*i; \
        cp16(su + 4*((2 + (p))*ASZ + r*36 + c4*4), \
             Bp + (size_t)(n0 + r)*K + kt + c4*4, 16); \
    } \
} while (0)

    int nch = K >> 5;   // K in {256,1024} -> nch in {8,32}
    ISSUE(0, 0); CP_COMMIT();
    ISSUE(1, 1); CP_COMMIT();

    int arow = warp_m*64 + (lane >> 2);
    int brow = warp_n*32 + (lane >> 2);
    int kcol = lane & 3;

    for (int c = 0; c < nch; c++) {
        int p = c & 1;
        CP_WAIT1();
        __syncthreads();
        const float* Ab = sm + p*ASZ;
        const float* Bb = sm + (2 + p)*ASZ;
#pragma unroll
        for (int ks = 0; ks < 4; ks++) {
            int k0 = ks*8 + kcol;
            uint32_t a[4][4], b[4][2];
#pragma unroll
            for (int i = 0; i < 4; i++) {
                int r = arow + i*16;
                a[i][0] = rna_tf32_u(Ab[r*36 + k0]);
                a[i][1] = rna_tf32_u(Ab[(r+8)*36 + k0]);
                a[i][2] = rna_tf32_u(Ab[r*36 + k0 + 4]);
                a[i][3] = rna_tf32_u(Ab[(r+8)*36 + k0 + 4]);
            }
#pragma unroll
            for (int j = 0; j < 4; j++) {
                int r = brow + j*8;
                b[j][0] = __float_as_uint(Bb[r*36 + k0]);
                b[j][1] = __float_as_uint(Bb[r*36 + k0 + 4]);
            }
#pragma unroll
            for (int i = 0; i < 4; i++)
#pragma unroll
                for (int j = 0; j < 4; j++)
                    MMA_TF32(d[i][j], a[i], b[j]);
        }
        __syncthreads();
        if (c + 2 < nch) ISSUE(c + 2, p);
        CP_COMMIT();
    }

    // ---------------- epilogue ----------------
    const float* bi = (epi == 2) ? (biasbase + (size_t)e*zbstride) : nullptr;
#pragma unroll
    for (int i = 0; i < 4; i++) {
        int rl = warp_m*64 + i*16 + (lane >> 2);
#pragma unroll
        for (int half = 0; half < 2; half++) {
            int gm = m0 + rl + half*8;
            if (gm >= Mloc) continue;
            int cr = cl ? cl[gm] : gm;
            float* cp = C + (size_t)cr*ldc;
#pragma unroll
            for (int j = 0; j < 4; j++) {
                int colc = warp_n*32 + j*8 + 2*(lane & 3);
                int gcol = n0 + colc;
                float v0 = d[i][j][half*2 + 0];
                float v1 = d[i][j][half*2 + 1];
                if (epi == 0) {
                    *reinterpret_cast<float2*>(cp + gcol) = make_float2(v0, v1);
                } else if (epi == 1) {
                    float2 o = *reinterpret_cast<float2*>(cp + gcol);
                    o.x += v0; o.y += v1;
                    *reinterpret_cast<float2*>(cp + gcol) = o;
                } else {
                    float x0 = v0 + bi[gcol];
                    float x1 = v1 + bi[gcol + 1];
                    x0 = 0.5f * x0 * (1.0f + erff(x0 * 0.70710678118654752f));
                    x1 = 0.5f * x1 * (1.0f + erff(x1 * 0.70710678118654752f));
                    *reinterpret_cast<float2*>(cp + gcol) = make_float2(x0, x1);
                }
            }
        }
    }
}

// ---------------- attention (one block per (batch, head)) ------------------
__global__ __launch_bounds__(128)
void attn_kernel(const float* __restrict__ wfreq, const float* __restrict__ wphase)
{
    int b = blockIdx.x >> 3, h = blockIdx.x & 7;
    __shared__ float ks[Lq*DKq];
    __shared__ float vs[Lq*DKq];
    __shared__ float wv[Lq];
    int tid = threadIdx.x;
    size_t base = (size_t)(b*Lq)*Dq + h*DKq;

    for (int idx = tid; idx < Lq*DKq; idx += 128) {
        int r = idx >> 5, c = idx & 31;
        size_t g = base + (size_t)r*Dq + c;
        ks[idx] = g_k[g];
        vs[idx] = g_v[g];
    }
    {
        float f = wfreq[h], ph = wphase[h];
        wv[tid] = cosf((6.2831853071795864f * f) * (float)tid + ph);
    }
    __syncthreads();

    float qr[DKq];
    const float4* qp = reinterpret_cast<const float4*>(g_q + base + (size_t)tid*Dq);
#pragma unroll
    for (int w = 0; w < 8; w++) {
        float4 f4 = qp[w];
        qr[4*w+0] = f4.x; qr[4*w+1] = f4.y; qr[4*w+2] = f4.z; qr[4*w+3] = f4.w;
    }

    float m = -1e30f, ssum = 0.f;
    float acc[DKq];
#pragma unroll
    for (int c = 0; c < DKq; c++) acc[c] = 0.f;
    const float scale = 0.17677669529663687f;

    for (int kk = 0; kk < Lq; kk++) {
        float s = 0.f;
#pragma unroll
        for (int c = 0; c < DKq; c++) s += qr[c] * ks[kk*DKq + c];
        s = s * scale * wv[kk];
        float mn = fmaxf(m, s);
        float corr = __expf(m - mn);
        float p = __expf(s - mn);
        ssum = ssum * corr + p;
#pragma unroll
        for (int c = 0; c < DKq; c++) acc[c] = acc[c]*corr + p*vs[kk*DKq + c];
        m = mn;
    }
    float inv = 1.f / ssum;
    float* op = g_att + base + (size_t)tid*Dq;
#pragma unroll
    for (int w = 0; w < 8; w++) {
        float4 f4 = make_float4(acc[4*w]*inv, acc[4*w+1]*inv, acc[4*w+2]*inv, acc[4*w+3]*inv);
        *reinterpret_cast<float4*>(op + 4*w) = f4;
    }
}

// ---------------- MoE router (one warp per token) --------------------------
__global__ __launch_bounds__(256)
void router_kernel(const float* __restrict__ rw, const float* __restrict__ rb, int layer)
{
    int warp = threadIdx.x >> 5, lane = threadIdx.x & 31;
    int t = (blockIdx.x << 3) + warp;

    float lg[Eq];
#pragma unroll
    for (int e = 0; e < Eq; e++) lg[e] = 0.f;
    const float* hp = g_h + (size_t)t*Dq;
    for (int kk = lane; kk < Dq; kk += 32) {
        float xv = hp[kk];
#pragma unroll
        for (int e = 0; e < Eq; e++) lg[e] += xv * rw[kk*Eq + e];
    }
#pragma unroll
    for (int e = 0; e < Eq; e++)
#pragma unroll
        for (int o = 16; o; o >>= 1) lg[e] += __shfl_xor_sync(0xffffffffu, lg[e], o);

    if (lane == 0) {
        float l[Eq], p[Eq];
        float mx = -1e30f;
#pragma unroll
        for (int e = 0; e < Eq; e++) { l[e] = lg[e] + rb[e]; mx = fmaxf(mx, l[e]); }
#pragma unroll
        for (int e = 0; e < Eq; e++) p[e] = __expf(l[e] - mx);
        int i0 = 0;
#pragma unroll
        for (int e = 1; e < Eq; e++) if (p[e] > p[i0]) i0 = e;
        int i1 = -1;
#pragma unroll
        for (int e = 0; e < Eq; e++) if (e != i0 && (i1 < 0 || p[e] > p[i1])) i1 = e;
        float w0 = p[i0], w1 = p[i1];
        float s2 = w0 + w1;
        w0 /= s2; w1 /= s2;

        int* cnt   = g_cnt  + layer*Eq;
        int* tokl  = g_tok  + (size_t)layer*Eq*NT;
        int* pairl = g_pair + (size_t)layer*Eq*NT;
        float* pwp = g_pw   + (size_t)layer*NP;
        int* pep   = g_pe   + (size_t)layer*NP;

        int p0 = atomicAdd(&cnt[i0], 1);
        tokl[i0*NT + p0] = t;  pairl[i0*NT + p0] = 2*t;
        int p1 = atomicAdd(&cnt[i1], 1);
        tokl[i1*NT + p1] = t;  pairl[i1*NT + p1] = 2*t + 1;
        pwp[2*t] = w0; pwp[2*t+1] = w1;
        pep[2*t] = i0; pep[2*t+1] = i1;
    }
}

// ---------------- MoE combine ----------------------------------------------
__global__ void moe_combine(const float* __restrict__ b2, int layer)
{
    int t = blockIdx.x, d = threadIdx.x;
    const float* pwp = g_pw + (size_t)layer*NP;
    const int*   pep = g_pe + (size_t)layer*NP;
    float w0 = pwp[2*t], w1 = pwp[2*t+1];
    int e0 = pep[2*t], e1 = pep[2*t+1];
    size_t i0 = (size_t)(2*t)*Dq + d;
    g_h[(size_t)t*Dq + d] += w0*(g_Y[i0]      + b2[e0*Dq + d])
                           + w1*(g_Y[i0 + Dq] + b2[e1*Dq + d]);
}

// ---------------- final LN + prediction heads ------------------------------
__global__ __launch_bounds__(256)
void head_kernel(const float* __restrict__ lng, const float* __restrict__ lnb,
                 const float* __restrict__ pw,  const float* __restrict__ pb,
                 const float* __restrict__ uw,  const float* __restrict__ ub,
                 float* __restrict__ out)
{
    int b = blockIdx.x, tid = threadIdx.x;
    int warp = tid >> 5, lane = tid & 31;
    __shared__ float z[Dq];
    __shared__ float red[8];

    size_t t = (size_t)b*Lq + (Lq - 1);
    float v = g_h[t*Dq + tid];

    float s = v;
#pragma unroll
    for (int o = 16; o; o >>= 1) s += __shfl_xor_sync(0xffffffffu, s, o);
    if (lane == 0) red[warp] = s;
    __syncthreads();
    float tot = 0.f;
#pragma unroll
    for (int i = 0; i < 8; i++) tot += red[i];
    float mean = tot * (1.f / Dq);
    __syncthreads();

    float dv = v - mean;
    float q = dv * dv;
#pragma unroll
    for (int o = 16; o; o >>= 1) q += __shfl_xor_sync(0xffffffffu, q, o);
    if (lane == 0) red[warp] = q;
    __syncthreads();
    float vtot = 0.f;
#pragma unroll
    for (int i = 0; i < 8; i++) vtot += red[i];
    float var = vtot * (1.f / Dq);

    z[tid] = dv * rsqrtf(var + 1e-5f) * lng[tid] + lnb[tid];
    __syncthreads();

    for (int o = warp; o < 2*NHq; o += 8) {
        int j = o % NHq;
        int isu = o / NHq;
        const float* W = isu ? uw : pw;
        float p = 0.f;
        for (int d = lane; d < Dq; d += 32) p += z[d] * W[d*NHq + j];
#pragma unroll
        for (int off = 16; off; off >>= 1) p += __shfl_xor_sync(0xffffffffu, p, off);
        if (lane == 0) {
            float r = p + (isu ? ub[j] : pb[j]);
            if (isu) r = fmaxf(r, 0.f) + log1pf(__expf(-fabsf(r)));
            out[isu*(Bq*NHq) + b*NHq + j] = r;
        }
    }
}

// ---------------- host side -----------------------------------------------
extern "C" void kernel_launch(void* const* d_in, const int* in_sizes, int n_in,
                              void* d_out, int out_size)
{
    const float* x      = (const float*)d_in[0];
    const float* embw   = (const float*)d_in[1];
    const float* embb   = (const float*)d_in[2];
    const float* qw     = (const float*)d_in[3];
    const float* kw     = (const float*)d_in[4];
    const float* vw     = (const float*)d_in[5];
    const float* ow     = (const float*)d_in[6];
    const float* wfreq  = (const float*)d_in[7];
    const float* wphase = (const float*)d_in[8];
    const float* rw     = (const float*)d_in[9];
    const float* rb     = (const float*)d_in[10];
    const float* ew1    = (const float*)d_in[11];
    const float* eb1    = (const float*)d_in[12];
    const float* ew2    = (const float*)d_in[13];
    const float* eb2    = (const float*)d_in[14];
    const float* lng    = (const float*)d_in[15];
    const float* lnb    = (const float*)d_in[16];
    const float* predw  = (const float*)d_in[17];
    const float* predb  = (const float*)d_in[18];
    const float* uncw   = (const float*)d_in[19];
    const float* uncb   = (const float*)d_in[20];
    float* out = (float*)d_out;

    float *h, *q, *k, *v, *att, *Hb, *Yb;
    float *qwt, *kwt, *vwt, *owt, *w1t, *w2t;
    int *cnt, *tok, *pair;
    cudaGetSymbolAddress((void**)&h,    g_h);
    cudaGetSymbolAddress((void**)&q,    g_q);
    cudaGetSymbolAddress((void**)&k,    g_k);
    cudaGetSymbolAddress((void**)&v,    g_v);
    cudaGetSymbolAddress((void**)&att,  g_att);
    cudaGetSymbolAddress((void**)&Hb,   g_H);
    cudaGetSymbolAddress((void**)&Yb,   g_Y);
    cudaGetSymbolAddress((void**)&cnt,  g_cnt);
    cudaGetSymbolAddress((void**)&tok,  g_tok);
    cudaGetSymbolAddress((void**)&pair, g_pair);
    cudaGetSymbolAddress((void**)&qwt,  g_qwt);
    cudaGetSymbolAddress((void**)&kwt,  g_kwt);
    cudaGetSymbolAddress((void**)&vwt,  g_vwt);
    cudaGetSymbolAddress((void**)&owt,  g_owt);
    cudaGetSymbolAddress((void**)&w1t,  g_w1t);
    cudaGetSymbolAddress((void**)&w2t,  g_w2t);

    cudaFuncSetAttribute(tc_gemm, cudaFuncAttributeMaxDynamicSharedMemorySize, SMEM_BYTES);

    // weight prep: transpose + tf32 rounding
    dim3 tb(32, 8);
    transpose_rna<<<dim3(Dq/32, Dq/32, NLq), tb>>>(qw, qwt, Dq, Dq);
    transpose_rna<<<dim3(Dq/32, Dq/32, NLq), tb>>>(kw, kwt, Dq, Dq);
    transpose_rna<<<dim3(Dq/32, Dq/32, NLq), tb>>>(vw, vwt, Dq, Dq);
    transpose_rna<<<dim3(Dq/32, Dq/32, NLq), tb>>>(ow, owt, Dq, Dq);
    transpose_rna<<<dim3(FFq/32, Dq/32, NMOEq*Eq), tb>>>(ew1, w1t, Dq, FFq);
    transpose_rna<<<dim3(Dq/32, FFq/32, NMOEq*Eq), tb>>>(ew2, w2t, FFq, Dq);

    zero_cnt_kernel<<<1, 32>>>();
    embed_kernel<<<NT, Dq>>>(x, embw, embb);

    dim3 gd(NT/128, Dq/128, 1);
    for (int i = 0; i < NLq; i++) {
        size_t wo = (size_t)i * Dq * Dq;
        tc_gemm<<<gd, 256, SMEM_BYTES>>>(h, qwt + wo, q, nullptr, NT, Dq, Dq,
                                         nullptr, nullptr, nullptr, 0, 0, 0, 0);
        tc_gemm<<<gd, 256, SMEM_BYTES>>>(h, kwt + wo, k, nullptr, NT, Dq, Dq,
                                         nullptr, nullptr, nullptr, 0, 0, 0, 0);
        tc_gemm<<<gd, 256, SMEM_BYTES>>>(h, vwt + wo, v, nullptr, NT, Dq, Dq,
                                         nullptr, nullptr, nullptr, 0, 0, 0, 0);
        attn_kernel<<<Bq*Hq, 128>>>(wfreq + i*Hq, wphase + i*Hq);
        tc_gemm<<<gd, 256, SMEM_BYTES>>>(att, owt + wo, h, nullptr, NT, Dq, Dq,
                                         nullptr, nullptr, nullptr, 0, 0, 0, 1);

        if ((i & 1) == 0) {
            int j = i >> 1;
            router_kernel<<<NT/8, 256>>>(rw + (size_t)j*Dq*Eq, rb + j*Eq, j);

            dim3 g1(NT/128, FFq/128, Eq);
            tc_gemm<<<g1, 256, SMEM_BYTES>>>(h, w1t + (size_t)j*Eq*FFq*Dq, Hb,
                                             eb1 + (size_t)j*Eq*FFq,
                                             0, Dq, FFq,
                                             cnt + j*Eq,
                                             tok  + (size_t)j*Eq*NT,
                                             pair + (size_t)j*Eq*NT,
                                             FFq*Dq, FFq, NT, 2);

            dim3 g2(NT/128, Dq/128, Eq);
            tc_gemm<<<g2, 256, SMEM_BYTES>>>(Hb, w2t + (size_t)j*Eq*Dq*FFq, Yb,
                                             nullptr,
                                             0, FFq, Dq,
                                             cnt + j*Eq,
                                             pair + (size_t)j*Eq*NT,
                                             pair + (size_t)j*Eq*NT,
                                             Dq*FFq, 0, NT, 0);

            moe_combine<<<NT, Dq>>>(eb2 + (size_t)j*Eq*Dq, j);
        }
    }

    head_kernel<<<Bq, 256>>>(lng, lnb, predw, predb, uncw, uncb, out);
}

// round 4
// speedup vs baseline: 3.3720x; 1.4196x over previous
#include <cuda_runtime.h>
#include <cuda_bf16.h>
#include <math.h>
#include <stdint.h>

// Problem constants
#define Bq   256
#define Lq   128
#define INDq 6
#define Dq   256
#define Hq   8
#define DKq  32
#define NLq  6
#define Eq   8
#define FFq  1024
#define NMOEq 3
#define NHq  5
#define NT   (Bq*Lq)      // 32768 tokens
#define NP   (2*NT)       // 65536 token-expert pairs
#define NQKV 768

// ---------------- scratch (device globals; no allocation allowed) ----------
__device__ __align__(16) float g_h  [NT*Dq];
__device__ __align__(16) __nv_bfloat16 g_hb [NT*Dq];
__device__ __align__(16) float g_qkv[NT*NQKV];
__device__ __align__(16) __nv_bfloat16 g_attb[NT*Dq];
__device__ __align__(16) __nv_bfloat16 g_Hb [NP*FFq];   // expert hidden (bf16)
__device__ __align__(16) float g_Y  [NP*Dq];
__device__ int   g_cnt [NMOEq*Eq];
__device__ int   g_tok [NMOEq*Eq*NT];
__device__ int   g_pair[NMOEq*Eq*NT];
__device__ float g_pw  [NMOEq*NP];
__device__ int   g_pe  [NMOEq*NP];
// transposed bf16 weights, [N,K] K-major
__device__ __align__(16) __nv_bfloat16 g_wqkvt[NLq*NQKV*Dq];
__device__ __align__(16) __nv_bfloat16 g_owtb [NLq*Dq*Dq];
__device__ __align__(16) __nv_bfloat16 g_w1tb [NMOEq*Eq*FFq*Dq];
__device__ __align__(16) __nv_bfloat16 g_w2tb [NMOEq*Eq*Dq*FFq];

// ---------------- helpers ---------------------------------------------------
__device__ __forceinline__ uint32_t smem_u32(const void* p) {
    uint32_t a;
    asm("{ .reg .u64 t; cvta.to.shared.u64 t, %1; cvt.u32.u64 %0, t; }" : "=r"(a) : "l"(p));
    return a;
}
__device__ __forceinline__ void cp16(uint32_t saddr, const void* g, int sz) {
    asm volatile("cp.async.ca.shared.global [%0], [%1], 16, %2;"
                 :: "r"(saddr), "l"(g), "r"(sz) : "memory");
}
#define CP_COMMIT()  asm volatile("cp.async.commit_group;" ::: "memory")
#define CP_WAIT1()   asm volatile("cp.async.wait_group 1;" ::: "memory")

#define LDSM4(r0, r1, r2, r3, addr) \
    asm volatile("ldmatrix.sync.aligned.m8n8.x4.shared.b16 {%0,%1,%2,%3}, [%4];" \
                 : "=r"(r0), "=r"(r1), "=r"(r2), "=r"(r3) : "r"(addr))

#define MMA_BF16(d, a, b) \
    asm volatile("mma.sync.aligned.m16n8k16.row.col.f32.bf16.bf16.f32 " \
                 "{%0,%1,%2,%3}, {%4,%5,%6,%7}, {%8,%9}, {%0,%1,%2,%3};" \
                 : "+f"((d)[0]), "+f"((d)[1]), "+f"((d)[2]), "+f"((d)[3]) \
                 : "r"((a)[0]), "r"((a)[1]), "r"((a)[2]), "r"((a)[3]), \
                   "r"((b)[0]), "r"((b)[1]))

// ---------------- small kernels -------------------------------------------
__global__ void zero_cnt_kernel() {
    if (threadIdx.x < NMOEq*Eq) g_cnt[threadIdx.x] = 0;
}

__global__ void embed_kernel(const float* __restrict__ x,
                             const float* __restrict__ w,
                             const float* __restrict__ b) {
    int t = blockIdx.x, d = threadIdx.x;
    float acc = b[d];
#pragma unroll
    for (int k = 0; k < INDq; k++) acc += x[t*INDq + k] * w[k*Dq + d];
    g_h [(size_t)t*Dq + d] = acc;
    g_hb[(size_t)t*Dq + d] = __float2bfloat16(acc);
}

// transpose to bf16: out[z*ostride + c*R + r] = bf16(in[z][r][c])
__global__ void transpose_b16(const float* __restrict__ in, __nv_bfloat16* __restrict__ out,
                              int R, int C, size_t ostride) {
    __shared__ float t[32][33];
    const float* ip = in + (size_t)blockIdx.z * R * C;
    __nv_bfloat16* op = out + (size_t)blockIdx.z * ostride;
    int c0 = blockIdx.x * 32, r0 = blockIdx.y * 32;
    int tx = threadIdx.x, ty = threadIdx.y;
#pragma unroll
    for (int j = 0; j < 32; j += 8)
        t[ty + j][tx] = ip[(size_t)(r0 + ty + j) * C + c0 + tx];
    __syncthreads();
#pragma unroll
    for (int j = 0; j < 32; j += 8)
        op[(size_t)(c0 + ty + j) * R + r0 + tx] = __float2bfloat16(t[tx][ty + j]);
}

// ---------------- bf16 warp-MMA GEMM (128x128 tile, BK=64 elems) -----------
// C[cidx[m]][:] (epi) = A[aidx[m]][:K] . Bt[n][:K]   (Bt [N,K] K-major bf16)
// epi: 0 = store fp32 C, 1 = residual add into C + bf16 copy to Cb,
//      2 = gelu(acc+bias) -> bf16 Cb only
#define SMA   16384              // bytes per A buffer (128 rows x 128B)
#define SMEM_BYTES (4*SMA)       // A0 A1 B0 B1 = 64KB

__global__ __launch_bounds__(256)
void bf_gemm(const __nv_bfloat16* __restrict__ A,
             const __nv_bfloat16* __restrict__ Btbase,
             float* __restrict__ C,
             __nv_bfloat16* __restrict__ Cb,
             const float* __restrict__ biasbase,
             int M, int K, int ldc, int ldcb,
             const int* __restrict__ cntp,
             const int* __restrict__ aidxb,
             const int* __restrict__ cidxb,
             int zBstride, int zbstride, int idxcap, int epi)
{
    extern __shared__ char sm[];
    int e = blockIdx.z;
    int Mloc = cntp ? cntp[e] : M;
    int m0 = blockIdx.x << 7;
    if (m0 >= Mloc) return;
    int n0 = blockIdx.y << 7;
    const __nv_bfloat16* Bp = Btbase + (size_t)e * zBstride;
    const int* al = aidxb ? aidxb + (size_t)e * idxcap : nullptr;
    const int* cl = cidxb ? cidxb + (size_t)e * idxcap : nullptr;

    int tid = threadIdx.x, wid = tid >> 5, lane = tid & 31;
    int warp_m = wid & 1, warp_n = wid >> 1;
    uint32_t su = smem_u32(sm);

    // loader geometry: thread covers rows (tid>>3)+32i, 16B group g=tid&7
    int gld = tid & 7;
    int srow0 = tid >> 3;

    int rowA[4], szA[4];
    uint32_t sw[4];     // swizzled smem offset for this thread's (row, group)
#pragma unroll
    for (int i = 0; i < 4; i++) {
        int r = srow0 + 32*i;
        int gm = m0 + r;
        bool v = gm < Mloc;
        rowA[i] = v ? (al ? al[gm] : gm) : 0;
        szA[i] = v ? 16 : 0;
        sw[i] = (uint32_t)(r*128 + ((gld ^ (r & 7)) << 4));
    }

    float d[4][4][4];
#pragma unroll
    for (int i = 0; i < 4; i++)
#pragma unroll
        for (int j = 0; j < 4; j++)
#pragma unroll
            for (int u = 0; u < 4; u++) d[i][j][u] = 0.f;

#define ISSUE(chunk, p) do { \
    int kt = (chunk) << 6; \
    _Pragma("unroll") \
    for (int i = 0; i < 4; i++) { \
        int r = srow0 + 32*i; \
        cp16(su + (p)*SMA + sw[i], A + (size_t)rowA[i]*K + kt + gld*8, szA[i]); \
        cp16(su + (2+(p))*SMA + sw[i], Bp + (size_t)(n0 + r)*K + kt + gld*8, 16); \
    } \
} while (0)

    int nch = K >> 6;        // 4 (K=256) or 16 (K=1024)
    ISSUE(0, 0); CP_COMMIT();
    ISSUE(1, 1); CP_COMMIT();

    // fragment-load lane geometry
    int ra = (lane & 15);            // A: row within m16 tile
    int ga_half = lane >> 4;         // A: k half
    int rb_in = ((lane >> 4) << 3) + (lane & 7);  // B: row within n16 pair
    int gb_half = (lane >> 3) & 1;   // B: k half

    for (int c = 0; c < nch; c++) {
        int p = c & 1;
        CP_WAIT1();
        __syncthreads();
        uint32_t Ab = su + p*SMA;
        uint32_t Bb = su + (2 + p)*SMA;
#pragma unroll
        for (int ks = 0; ks < 4; ks++) {
            uint32_t a[4][4], b[4][2];
#pragma unroll
            for (int i = 0; i < 4; i++) {
                int r = warp_m*64 + i*16 + ra;
                int g = ks*2 + ga_half;
                LDSM4(a[i][0], a[i][1], a[i][2], a[i][3],
                      Ab + r*128 + ((g ^ (r & 7)) << 4));
            }
#pragma unroll
            for (int j2 = 0; j2 < 2; j2++) {
                int r = warp_n*32 + j2*16 + rb_in;
                int g = ks*2 + gb_half;
                LDSM4(b[2*j2][0], b[2*j2][1], b[2*j2+1][0], b[2*j2+1][1],
                      Bb + r*128 + ((g ^ (r & 7)) << 4));
            }
#pragma unroll
            for (int i = 0; i < 4; i++)
#pragma unroll
                for (int j = 0; j < 4; j++)
                    MMA_BF16(d[i][j], a[i], b[j]);
        }
        __syncthreads();
        if (c + 2 < nch) ISSUE(c + 2, p);
        CP_COMMIT();
    }

    // ---------------- epilogue ----------------
    const float* bi = (epi == 2) ? (biasbase + (size_t)e*zbstride) : nullptr;
#pragma unroll
    for (int i = 0; i < 4; i++) {
        int rl = warp_m*64 + i*16 + (lane >> 2);
#pragma unroll
        for (int half = 0; half < 2; half++) {
            int gm = m0 + rl + half*8;
            if (gm >= Mloc) continue;
            int cr = cl ? cl[gm] : gm;
#pragma unroll
            for (int j = 0; j < 4; j++) {
                int gcol = n0 + warp_n*32 + j*8 + 2*(lane & 3);
                float v0 = d[i][j][half*2 + 0];
                float v1 = d[i][j][half*2 + 1];
                if (epi == 0) {
                    *reinterpret_cast<float2*>(C + (size_t)cr*ldc + gcol) = make_float2(v0, v1);
                } else if (epi == 1) {
                    float* cp = C + (size_t)cr*ldc + gcol;
                    float2 o = *reinterpret_cast<float2*>(cp);
                    o.x += v0; o.y += v1;
                    *reinterpret_cast<float2*>(cp) = o;
                    __nv_bfloat162 bb;
                    bb.x = __float2bfloat16(o.x); bb.y = __float2bfloat16(o.y);
                    *reinterpret_cast<__nv_bfloat162*>(Cb + (size_t)cr*ldcb + gcol) = bb;
                } else {
                    float x0 = v0 + bi[gcol];
                    float x1 = v1 + bi[gcol + 1];
                    x0 = 0.5f * x0 * (1.0f + erff(x0 * 0.70710678118654752f));
                    x1 = 0.5f * x1 * (1.0f + erff(x1 * 0.70710678118654752f));
                    __nv_bfloat162 bb;
                    bb.x = __float2bfloat16(x0); bb.y = __float2bfloat16(x1);
                    *reinterpret_cast<__nv_bfloat162*>(Cb + (size_t)cr*ldcb + gcol) = bb;
                }
            }
        }
    }
}

// ---------------- attention (one block per (batch, head)) ------------------
// q,k,v live in g_qkv (ld=768): q at col h*32, k at 256+h*32, v at 512+h*32
__global__ __launch_bounds__(128)
void attn_kernel(const float* __restrict__ wfreq, const float* __restrict__ wphase)
{
    int b = blockIdx.x >> 3, h = blockIdx.x & 7;
    __shared__ float ks[Lq*DKq];
    __shared__ float vs[Lq*DKq];
    __shared__ float wv[Lq];
    int tid = threadIdx.x;
    size_t rowbase = (size_t)(b*Lq)*NQKV;

    for (int idx = tid; idx < Lq*DKq; idx += 128) {
        int r = idx >> 5, c = idx & 31;
        size_t g = rowbase + (size_t)r*NQKV + h*DKq + c;
        ks[idx] = g_qkv[g + 256];
        vs[idx] = g_qkv[g + 512];
    }
    {
        float f = wfreq[h], ph = wphase[h];
        wv[tid] = cosf((6.2831853071795864f * f) * (float)tid + ph);
    }
    __syncthreads();

    float qr[DKq];
    const float4* qp = reinterpret_cast<const float4*>(g_qkv + rowbase + (size_t)tid*NQKV + h*DKq);
#pragma unroll
    for (int w = 0; w < 8; w++) {
        float4 f4 = qp[w];
        qr[4*w+0] = f4.x; qr[4*w+1] = f4.y; qr[4*w+2] = f4.z; qr[4*w+3] = f4.w;
    }

    float m = -1e30f, ssum = 0.f;
    float acc[DKq];
#pragma unroll
    for (int c = 0; c < DKq; c++) acc[c] = 0.f;
    const float scale = 0.17677669529663687f;

    for (int kk = 0; kk < Lq; kk++) {
        float s = 0.f;
#pragma unroll
        for (int c = 0; c < DKq; c++) s += qr[c] * ks[kk*DKq + c];
        s = s * scale * wv[kk];
        float mn = fmaxf(m, s);
        float corr = __expf(m - mn);
        float p = __expf(s - mn);
        ssum = ssum * corr + p;
#pragma unroll
        for (int c = 0; c < DKq; c++) acc[c] = acc[c]*corr + p*vs[kk*DKq + c];
        m = mn;
    }
    float inv = 1.f / ssum;
    __nv_bfloat16* op = g_attb + (size_t)(b*Lq + tid)*Dq + h*DKq;
#pragma unroll
    for (int w = 0; w < 16; w++) {
        __nv_bfloat162 bb;
        bb.x = __float2bfloat16(acc[2*w]   * inv);
        bb.y = __float2bfloat16(acc[2*w+1] * inv);
        *reinterpret_cast<__nv_bfloat162*>(op + 2*w) = bb;
    }
}

// ---------------- MoE router (one warp per token) --------------------------
__global__ __launch_bounds__(256)
void router_kernel(const float* __restrict__ rw, const float* __restrict__ rb, int layer)
{
    int warp = threadIdx.x >> 5, lane = threadIdx.x & 31;
    int t = (blockIdx.x << 3) + warp;

    float lg[Eq];
#pragma unroll
    for (int e = 0; e < Eq; e++) lg[e] = 0.f;
    const float* hp = g_h + (size_t)t*Dq;
    for (int kk = lane; kk < Dq; kk += 32) {
        float xv = hp[kk];
#pragma unroll
        for (int e = 0; e < Eq; e++) lg[e] += xv * rw[kk*Eq + e];
    }
#pragma unroll
    for (int e = 0; e < Eq; e++)
#pragma unroll
        for (int o = 16; o; o >>= 1) lg[e] += __shfl_xor_sync(0xffffffffu, lg[e], o);

    if (lane == 0) {
        float l[Eq], p[Eq];
        float mx = -1e30f;
#pragma unroll
        for (int e = 0; e < Eq; e++) { l[e] = lg[e] + rb[e]; mx = fmaxf(mx, l[e]); }
#pragma unroll
        for (int e = 0; e < Eq; e++) p[e] = __expf(l[e] - mx);
        int i0 = 0;
#pragma unroll
        for (int e = 1; e < Eq; e++) if (p[e] > p[i0]) i0 = e;
        int i1 = -1;
#pragma unroll
        for (int e = 0; e < Eq; e++) if (e != i0 && (i1 < 0 || p[e] > p[i1])) i1 = e;
        float w0 = p[i0], w1 = p[i1];
        float s2 = w0 + w1;
        w0 /= s2; w1 /= s2;

        int* cnt   = g_cnt  + layer*Eq;
        int* tokl  = g_tok  + (size_t)layer*Eq*NT;
        int* pairl = g_pair + (size_t)layer*Eq*NT;
        float* pwp = g_pw   + (size_t)layer*NP;
        int* pep   = g_pe   + (size_t)layer*NP;

        int p0 = atomicAdd(&cnt[i0], 1);
        tokl[i0*NT + p0] = t;  pairl[i0*NT + p0] = 2*t;
        int p1 = atomicAdd(&cnt[i1], 1);
        tokl[i1*NT + p1] = t;  pairl[i1*NT + p1] = 2*t + 1;
        pwp[2*t] = w0; pwp[2*t+1] = w1;
        pep[2*t] = i0; pep[2*t+1] = i1;
    }
}

// ---------------- MoE combine (updates h and hb) ---------------------------
__global__ void moe_combine(const float* __restrict__ b2, int layer)
{
    int t = blockIdx.x, d = threadIdx.x;
    const float* pwp = g_pw + (size_t)layer*NP;
    const int*   pep = g_pe + (size_t)layer*NP;
    float w0 = pwp[2*t], w1 = pwp[2*t+1];
    int e0 = pep[2*t], e1 = pep[2*t+1];
    size_t i0 = (size_t)(2*t)*Dq + d;
    float nv = g_h[(size_t)t*Dq + d]
             + w0*(g_Y[i0]      + b2[e0*Dq + d])
             + w1*(g_Y[i0 + Dq] + b2[e1*Dq + d]);
    g_h [(size_t)t*Dq + d] = nv;
    g_hb[(size_t)t*Dq + d] = __float2bfloat16(nv);
}

// ---------------- final LN + prediction heads ------------------------------
__global__ __launch_bounds__(256)
void head_kernel(const float* __restrict__ lng, const float* __restrict__ lnb,
                 const float* __restrict__ pw,  const float* __restrict__ pb,
                 const float* __restrict__ uw,  const float* __restrict__ ub,
                 float* __restrict__ out)
{
    int b = blockIdx.x, tid = threadIdx.x;
    int warp = tid >> 5, lane = tid & 31;
    __shared__ float z[Dq];
    __shared__ float red[8];

    size_t t = (size_t)b*Lq + (Lq - 1);
    float v = g_h[t*Dq + tid];

    float s = v;
#pragma unroll
    for (int o = 16; o; o >>= 1) s += __shfl_xor_sync(0xffffffffu, s, o);
    if (lane == 0) red[warp] = s;
    __syncthreads();
    float tot = 0.f;
#pragma unroll
    for (int i = 0; i < 8; i++) tot += red[i];
    float mean = tot * (1.f / Dq);
    __syncthreads();

    float dv = v - mean;
    float q = dv * dv;
#pragma unroll
    for (int o = 16; o; o >>= 1) q += __shfl_xor_sync(0xffffffffu, q, o);
    if (lane == 0) red[warp] = q;
    __syncthreads();
    float vtot = 0.f;
#pragma unroll
    for (int i = 0; i < 8; i++) vtot += red[i];
    float var = vtot * (1.f / Dq);

    z[tid] = dv * rsqrtf(var + 1e-5f) * lng[tid] + lnb[tid];
    __syncthreads();

    for (int o = warp; o < 2*NHq; o += 8) {
        int j = o % NHq;
        int isu = o / NHq;
        const float* W = isu ? uw : pw;
        float p = 0.f;
        for (int d = lane; d < Dq; d += 32) p += z[d] * W[d*NHq + j];
#pragma unroll
        for (int off = 16; off; off >>= 1) p += __shfl_xor_sync(0xffffffffu, p, off);
        if (lane == 0) {
            float r = p + (isu ? ub[j] : pb[j]);
            if (isu) r = fmaxf(r, 0.f) + log1pf(__expf(-fabsf(r)));
            out[isu*(Bq*NHq) + b*NHq + j] = r;
        }
    }
}

// ---------------- host side -----------------------------------------------
extern "C" void kernel_launch(void* const* d_in, const int* in_sizes, int n_in,
                              void* d_out, int out_size)
{
    const float* x      = (const float*)d_in[0];
    const float* embw   = (const float*)d_in[1];
    const float* embb   = (const float*)d_in[2];
    const float* qw     = (const float*)d_in[3];
    const float* kw     = (const float*)d_in[4];
    const float* vw     = (const float*)d_in[5];
    const float* ow     = (const float*)d_in[6];
    const float* wfreq  = (const float*)d_in[7];
    const float* wphase = (const float*)d_in[8];
    const float* rw     = (const float*)d_in[9];
    const float* rb     = (const float*)d_in[10];
    const float* ew1    = (const float*)d_in[11];
    const float* eb1    = (const float*)d_in[12];
    const float* ew2    = (const float*)d_in[13];
    const float* eb2    = (const float*)d_in[14];
    const float* lng    = (const float*)d_in[15];
    const float* lnb    = (const float*)d_in[16];
    const float* predw  = (const float*)d_in[17];
    const float* predb  = (const float*)d_in[18];
    const float* uncw   = (const float*)d_in[19];
    const float* uncb   = (const float*)d_in[20];
    float* out = (float*)d_out;

    float *h, *qkv, *Yb;
    __nv_bfloat16 *hb, *attb, *Hb, *wqkvt, *owtb, *w1tb, *w2tb;
    int *cnt, *tok, *pair;
    cudaGetSymbolAddress((void**)&h,     g_h);
    cudaGetSymbolAddress((void**)&hb,    g_hb);
    cudaGetSymbolAddress((void**)&qkv,   g_qkv);
    cudaGetSymbolAddress((void**)&attb,  g_attb);
    cudaGetSymbolAddress((void**)&Hb,    g_Hb);
    cudaGetSymbolAddress((void**)&Yb,    g_Y);
    cudaGetSymbolAddress((void**)&cnt,   g_cnt);
    cudaGetSymbolAddress((void**)&tok,   g_tok);
    cudaGetSymbolAddress((void**)&pair,  g_pair);
    cudaGetSymbolAddress((void**)&wqkvt, g_wqkvt);
    cudaGetSymbolAddress((void**)&owtb,  g_owtb);
    cudaGetSymbolAddress((void**)&w1tb,  g_w1tb);
    cudaGetSymbolAddress((void**)&w2tb,  g_w2tb);

    cudaFuncSetAttribute(bf_gemm, cudaFuncAttributeMaxDynamicSharedMemorySize, SMEM_BYTES);

    // weight prep: transpose + bf16 (QKV concatenated to [768,256] per layer)
    dim3 tb(32, 8);
    transpose_b16<<<dim3(8, 8, NLq), tb>>>(qw, wqkvt,            Dq, Dq, (size_t)NQKV*Dq);
    transpose_b16<<<dim3(8, 8, NLq), tb>>>(kw, wqkvt + 256*Dq,   Dq, Dq, (size_t)NQKV*Dq);
    transpose_b16<<<dim3(8, 8, NLq), tb>>>(vw, wqkvt + 512*Dq,   Dq, Dq, (size_t)NQKV*Dq);
    transpose_b16<<<dim3(8, 8, NLq), tb>>>(ow, owtb,             Dq, Dq, (size_t)Dq*Dq);
    transpose_b16<<<dim3(FFq/32, Dq/32, NMOEq*Eq), tb>>>(ew1, w1tb, Dq, FFq, (size_t)FFq*Dq);
    transpose_b16<<<dim3(Dq/32, FFq/32, NMOEq*Eq), tb>>>(ew2, w2tb, FFq, Dq, (size_t)Dq*FFq);

    zero_cnt_kernel<<<1, 32>>>();
    embed_kernel<<<NT, Dq>>>(x, embw, embb);

    for (int i = 0; i < NLq; i++) {
        // fused QKV projection: [NT,256] x [768,256]^T -> g_qkv [NT,768]
        bf_gemm<<<dim3(NT/128, NQKV/128, 1), 256, SMEM_BYTES>>>(
            hb, wqkvt + (size_t)i*NQKV*Dq, qkv, nullptr, nullptr,
            NT, Dq, NQKV, 0, nullptr, nullptr, nullptr, 0, 0, 0, 0);

        attn_kernel<<<Bq*Hq, 128>>>(wfreq + i*Hq, wphase + i*Hq);

        // O projection + residual (writes h fp32 and hb bf16)
        bf_gemm<<<dim3(NT/128, Dq/128, 1), 256, SMEM_BYTES>>>(
            attb, owtb + (size_t)i*Dq*Dq, h, hb, nullptr,
            NT, Dq, Dq, Dq, nullptr, nullptr, nullptr, 0, 0, 0, 1);

        if ((i & 1) == 0) {
            int j = i >> 1;
            router_kernel<<<NT/8, 256>>>(rw + (size_t)j*Dq*Eq, rb + j*Eq, j);

            // expert up-proj + gelu -> Hb (bf16)
            bf_gemm<<<dim3(NT/128, FFq/128, Eq), 256, SMEM_BYTES>>>(
                hb, w1tb + (size_t)j*Eq*FFq*Dq, nullptr, Hb,
                eb1 + (size_t)j*Eq*FFq,
                0, Dq, 0, FFq,
                cnt + j*Eq, tok + (size_t)j*Eq*NT, pair + (size_t)j*Eq*NT,
                FFq*Dq, FFq, NT, 2);

            // expert down-proj -> Y (fp32)
            bf_gemm<<<dim3(NT/128, Dq/128, Eq), 256, SMEM_BYTES>>>(
                Hb, w2tb + (size_t)j*Eq*Dq*FFq, Yb, nullptr, nullptr,
                0, FFq, Dq, 0,
                cnt + j*Eq, pair + (size_t)j*Eq*NT, pair + (size_t)j*Eq*NT,
                Dq*FFq, 0, NT, 0);

            moe_combine<<<NT, Dq>>>(eb2 + (size_t)j*Eq*Dq, j);
        }
    }

    head_kernel<<<Bq, 256>>>(lng, lnb, predw, predb, uncw, uncb, out);
}

// round 5
// speedup vs baseline: 4.7849x; 1.4190x over previous
#include <cuda_runtime.h>
#include <cuda_fp16.h>
#include <math.h>
#include <stdint.h>

// Problem constants
#define Bq   256
#define Lq   128
#define INDq 6
#define Dq   256
#define Hq   8
#define DKq  32
#define NLq  6
#define Eq   8
#define FFq  1024
#define NMOEq 3
#define NHq  5
#define NT   (Bq*Lq)      // 32768 tokens
#define NP   (2*NT)       // 65536 token-expert pairs
#define NQKV 768

// ---------------- scratch (device globals; no allocation allowed) ----------
__device__ __align__(16) float  g_h   [NT*Dq];
__device__ __align__(16) __half g_hb  [NT*Dq];
__device__ __align__(16) __half g_qkvh[NT*NQKV];
__device__ __align__(16) __half g_attb[NT*Dq];
__device__ __align__(16) __half g_Hb  [NP*FFq];
__device__ __align__(16) float  g_Y   [NP*Dq];
__device__ int   g_cnt [NMOEq*Eq];
__device__ int   g_tok [NMOEq*Eq*NT];
__device__ int   g_pair[NMOEq*Eq*NT];
__device__ float g_pw  [NMOEq*NP];
__device__ int   g_pe  [NMOEq*NP];
// transposed fp16 weights, [N,K] K-major
__device__ __align__(16) __half g_wqkvt[NLq*NQKV*Dq];
__device__ __align__(16) __half g_owtb [NLq*Dq*Dq];
__device__ __align__(16) __half g_w1tb [NMOEq*Eq*FFq*Dq];
__device__ __align__(16) __half g_w2tb [NMOEq*Eq*Dq*FFq];

// ---------------- helpers ---------------------------------------------------
__device__ __forceinline__ uint32_t smem_u32(const void* p) {
    uint32_t a;
    asm("{ .reg .u64 t; cvta.to.shared.u64 t, %1; cvt.u32.u64 %0, t; }" : "=r"(a) : "l"(p));
    return a;
}
__device__ __forceinline__ void cp16(uint32_t saddr, const void* g, int sz) {
    asm volatile("cp.async.ca.shared.global [%0], [%1], 16, %2;"
                 :: "r"(saddr), "l"(g), "r"(sz) : "memory");
}
#define CP_COMMIT()  asm volatile("cp.async.commit_group;" ::: "memory")
#define CP_WAIT1()   asm volatile("cp.async.wait_group 1;" ::: "memory")

#define LDSM4(r0, r1, r2, r3, addr) \
    asm volatile("ldmatrix.sync.aligned.m8n8.x4.shared.b16 {%0,%1,%2,%3}, [%4];" \
                 : "=r"(r0), "=r"(r1), "=r"(r2), "=r"(r3) : "r"(addr))

#define MMA_F16(d, a, b) \
    asm volatile("mma.sync.aligned.m16n8k16.row.col.f32.f16.f16.f32 " \
                 "{%0,%1,%2,%3}, {%4,%5,%6,%7}, {%8,%9}, {%0,%1,%2,%3};" \
                 : "+f"((d)[0]), "+f"((d)[1]), "+f"((d)[2]), "+f"((d)[3]) \
                 : "r"((a)[0]), "r"((a)[1]), "r"((a)[2]), "r"((a)[3]), \
                   "r"((b)[0]), "r"((b)[1]))

__device__ __forceinline__ uint32_t pack_h2(float lo, float hi) {
    __half2 h = __floats2half2_rn(lo, hi);
    return *reinterpret_cast<uint32_t*>(&h);
}

// ---------------- small kernels -------------------------------------------
__global__ void zero_cnt_kernel() {
    if (threadIdx.x < NMOEq*Eq) g_cnt[threadIdx.x] = 0;
}

__global__ void embed_kernel(const float* __restrict__ x,
                             const float* __restrict__ w,
                             const float* __restrict__ b) {
    int t = blockIdx.x, d = threadIdx.x;
    float acc = b[d];
#pragma unroll
    for (int k = 0; k < INDq; k++) acc += x[t*INDq + k] * w[k*Dq + d];
    g_h [(size_t)t*Dq + d] = acc;
    g_hb[(size_t)t*Dq + d] = __float2half(acc);
}

// transpose to fp16: out[z*ostride + c*R + r] = h16(in[z][r][c])
__global__ void transpose_h16(const float* __restrict__ in, __half* __restrict__ out,
                              int R, int C, size_t ostride) {
    __shared__ float t[32][33];
    const float* ip = in + (size_t)blockIdx.z * R * C;
    __half* op = out + (size_t)blockIdx.z * ostride;
    int c0 = blockIdx.x * 32, r0 = blockIdx.y * 32;
    int tx = threadIdx.x, ty = threadIdx.y;
#pragma unroll
    for (int j = 0; j < 32; j += 8)
        t[ty + j][tx] = ip[(size_t)(r0 + ty + j) * C + c0 + tx];
    __syncthreads();
#pragma unroll
    for (int j = 0; j < 32; j += 8)
        op[(size_t)(c0 + ty + j) * R + r0 + tx] = __float2half(t[tx][ty + j]);
}

// ---------------- fp16 warp-MMA GEMM (128x128 tile, BK=64 elems) -----------
// epi: 0 = fp32 C; 1 = residual add C + fp16 Cb; 2 = gelu(acc+bias)->Cb;
//      3 = plain fp16 Cb
#define SMA   16384
#define SMEM_BYTES (4*SMA)

__global__ __launch_bounds__(256)
void hgemm(const __half* __restrict__ A,
           const __half* __restrict__ Btbase,
           float* __restrict__ C,
           __half* __restrict__ Cb,
           const float* __restrict__ biasbase,
           int M, int K, int ldc, int ldcb,
           const int* __restrict__ cntp,
           const int* __restrict__ aidxb,
           const int* __restrict__ cidxb,
           int zBstride, int zbstride, int idxcap, int epi)
{
    extern __shared__ char sm[];
    int e = blockIdx.z;
    int Mloc = cntp ? cntp[e] : M;
    int m0 = blockIdx.x << 7;
    if (m0 >= Mloc) return;
    int n0 = blockIdx.y << 7;
    const __half* Bp = Btbase + (size_t)e * zBstride;
    const int* al = aidxb ? aidxb + (size_t)e * idxcap : nullptr;
    const int* cl = cidxb ? cidxb + (size_t)e * idxcap : nullptr;

    int tid = threadIdx.x, wid = tid >> 5, lane = tid & 31;
    int warp_m = wid & 1, warp_n = wid >> 1;
    uint32_t su = smem_u32(sm);

    int gld = tid & 7;
    int srow0 = tid >> 3;

    int rowA[4], szA[4];
    uint32_t sw[4];
#pragma unroll
    for (int i = 0; i < 4; i++) {
        int r = srow0 + 32*i;
        int gm = m0 + r;
        bool v = gm < Mloc;
        rowA[i] = v ? (al ? al[gm] : gm) : 0;
        szA[i] = v ? 16 : 0;
        sw[i] = (uint32_t)(r*128 + ((gld ^ (r & 7)) << 4));
    }

    float d[4][4][4];
#pragma unroll
    for (int i = 0; i < 4; i++)
#pragma unroll
        for (int j = 0; j < 4; j++)
#pragma unroll
            for (int u = 0; u < 4; u++) d[i][j][u] = 0.f;

#define ISSUE(chunk, p) do { \
    int kt = (chunk) << 6; \
    _Pragma("unroll") \
    for (int i = 0; i < 4; i++) { \
        int r = srow0 + 32*i; \
        cp16(su + (p)*SMA + sw[i], A + (size_t)rowA[i]*K + kt + gld*8, szA[i]); \
        cp16(su + (2+(p))*SMA + sw[i], Bp + (size_t)(n0 + r)*K + kt + gld*8, 16); \
    } \
} while (0)

    int nch = K >> 6;
    ISSUE(0, 0); CP_COMMIT();
    ISSUE(1, 1); CP_COMMIT();

    int ra = (lane & 15);
    int ga_half = lane >> 4;
    int rb_in = ((lane >> 4) << 3) + (lane & 7);
    int gb_half = (lane >> 3) & 1;

    for (int c = 0; c < nch; c++) {
        int p = c & 1;
        CP_WAIT1();
        __syncthreads();
        uint32_t Ab = su + p*SMA;
        uint32_t Bb = su + (2 + p)*SMA;
#pragma unroll
        for (int ks = 0; ks < 4; ks++) {
            uint32_t a[4][4], b[4][2];
#pragma unroll
            for (int i = 0; i < 4; i++) {
                int r = warp_m*64 + i*16 + ra;
                int g = ks*2 + ga_half;
                LDSM4(a[i][0], a[i][1], a[i][2], a[i][3],
                      Ab + r*128 + ((g ^ (r & 7)) << 4));
            }
#pragma unroll
            for (int j2 = 0; j2 < 2; j2++) {
                int r = warp_n*32 + j2*16 + rb_in;
                int g = ks*2 + gb_half;
                LDSM4(b[2*j2][0], b[2*j2][1], b[2*j2+1][0], b[2*j2+1][1],
                      Bb + r*128 + ((g ^ (r & 7)) << 4));
            }
#pragma unroll
            for (int i = 0; i < 4; i++)
#pragma unroll
                for (int j = 0; j < 4; j++)
                    MMA_F16(d[i][j], a[i], b[j]);
        }
        __syncthreads();
        if (c + 2 < nch) ISSUE(c + 2, p);
        CP_COMMIT();
    }

    const float* bi = (epi == 2) ? (biasbase + (size_t)e*zbstride) : nullptr;
#pragma unroll
    for (int i = 0; i < 4; i++) {
        int rl = warp_m*64 + i*16 + (lane >> 2);
#pragma unroll
        for (int half = 0; half < 2; half++) {
            int gm = m0 + rl + half*8;
            if (gm >= Mloc) continue;
            int cr = cl ? cl[gm] : gm;
#pragma unroll
            for (int j = 0; j < 4; j++) {
                int gcol = n0 + warp_n*32 + j*8 + 2*(lane & 3);
                float v0 = d[i][j][half*2 + 0];
                float v1 = d[i][j][half*2 + 1];
                if (epi == 0) {
                    *reinterpret_cast<float2*>(C + (size_t)cr*ldc + gcol) = make_float2(v0, v1);
                } else if (epi == 1) {
                    float* cp = C + (size_t)cr*ldc + gcol;
                    float2 o = *reinterpret_cast<float2*>(cp);
                    o.x += v0; o.y += v1;
                    *reinterpret_cast<float2*>(cp) = o;
                    *reinterpret_cast<__half2*>(Cb + (size_t)cr*ldcb + gcol) =
                        __floats2half2_rn(o.x, o.y);
                } else if (epi == 2) {
                    float x0 = v0 + bi[gcol];
                    float x1 = v1 + bi[gcol + 1];
                    x0 = 0.5f * x0 * (1.0f + erff(x0 * 0.70710678118654752f));
                    x1 = 0.5f * x1 * (1.0f + erff(x1 * 0.70710678118654752f));
                    *reinterpret_cast<__half2*>(Cb + (size_t)cr*ldcb + gcol) =
                        __floats2half2_rn(x0, x1);
                } else {
                    *reinterpret_cast<__half2*>(Cb + (size_t)cr*ldcb + gcol) =
                        __floats2half2_rn(v0, v1);
                }
            }
        }
    }
}

// ---------------- tensor-core attention ------------------------------------
// one block per (batch, head); 8 warps, warp w = query rows 16w..16w+15
#define QK_STR 40     // halves per row (80B, 16B-aligned, conflict-free)
#define VT_STR 136    // halves per row (272B)

__global__ __launch_bounds__(256)
void attn_tc(const float* __restrict__ wfreq, const float* __restrict__ wphase)
{
    __shared__ __half sQ[128*QK_STR];
    __shared__ __half sK[128*QK_STR];
    __shared__ __half sVt[32*VT_STR];
    __shared__ float  wv[Lq];

    int b = blockIdx.x >> 3, h = blockIdx.x & 7;
    int tid = threadIdx.x, wid = tid >> 5, lane = tid & 31;
    const __half* src = g_qkvh + (size_t)(b*Lq)*NQKV + h*DKq;

    // load Q, K (vectorized), V transposed
#pragma unroll
    for (int it = 0; it < 2; it++) {
        int i = tid + (it << 8);
        int r = i >> 2, g = i & 3;
        const __half* rp = src + (size_t)r*NQKV;
        *reinterpret_cast<uint4*>(&sQ[r*QK_STR + g*8]) =
            *reinterpret_cast<const uint4*>(rp + g*8);
        *reinterpret_cast<uint4*>(&sK[r*QK_STR + g*8]) =
            *reinterpret_cast<const uint4*>(rp + 256 + g*8);
        uint4 vv = *reinterpret_cast<const uint4*>(rp + 512 + g*8);
        const __half* vh = reinterpret_cast<const __half*>(&vv);
#pragma unroll
        for (int u = 0; u < 8; u++)
            sVt[(g*8 + u)*VT_STR + r] = vh[u];
    }
    if (tid < Lq) {
        float f = wfreq[h], ph = wphase[h];
        wv[tid] = cosf((6.2831853071795864f * f) * (float)tid + ph) * 0.17677669529663687f;
    }
    __syncthreads();

    uint32_t sQu = smem_u32(sQ), sKu = smem_u32(sK), sVtu = smem_u32(sVt);
    int rb_in = ((lane >> 4) << 3) + (lane & 7);
    int gb_half = (lane >> 3) & 1;

    // ---- S = Q K^T  (16 rows x 128 cols per warp) ----
    float s[16][4];
#pragma unroll
    for (int j = 0; j < 16; j++)
#pragma unroll
        for (int u = 0; u < 4; u++) s[j][u] = 0.f;

#pragma unroll
    for (int ks = 0; ks < 2; ks++) {
        uint32_t a[4];
        LDSM4(a[0], a[1], a[2], a[3],
              sQu + (wid*16 + (lane & 15))*(QK_STR*2) + (ks*16 + (lane >> 4)*8)*2);
#pragma unroll
        for (int j2 = 0; j2 < 8; j2++) {
            uint32_t b0[2], b1[2];
            LDSM4(b0[0], b0[1], b1[0], b1[1],
                  sKu + (j2*16 + rb_in)*(QK_STR*2) + (ks*16 + gb_half*8)*2);
            MMA_F16(s[2*j2],   a, b0);
            MMA_F16(s[2*j2+1], a, b1);
        }
    }

    // ---- wave modulate + softmax (rows r1 = 16w + l>>2, r2 = r1+8) ----
    int lc = 2*(lane & 3);
    float m1 = -1e30f, m2 = -1e30f;
#pragma unroll
    for (int j = 0; j < 16; j++) {
        float w0 = wv[8*j + lc], w1 = wv[8*j + lc + 1];
        s[j][0] *= w0; s[j][1] *= w1; s[j][2] *= w0; s[j][3] *= w1;
        m1 = fmaxf(m1, fmaxf(s[j][0], s[j][1]));
        m2 = fmaxf(m2, fmaxf(s[j][2], s[j][3]));
    }
#pragma unroll
    for (int o = 1; o <= 2; o <<= 1) {
        m1 = fmaxf(m1, __shfl_xor_sync(0xffffffffu, m1, o));
        m2 = fmaxf(m2, __shfl_xor_sync(0xffffffffu, m2, o));
    }
    float sum1 = 0.f, sum2 = 0.f;
#pragma unroll
    for (int j = 0; j < 16; j++) {
        s[j][0] = __expf(s[j][0] - m1); s[j][1] = __expf(s[j][1] - m1);
        s[j][2] = __expf(s[j][2] - m2); s[j][3] = __expf(s[j][3] - m2);
        sum1 += s[j][0] + s[j][1];
        sum2 += s[j][2] + s[j][3];
    }
#pragma unroll
    for (int o = 1; o <= 2; o <<= 1) {
        sum1 += __shfl_xor_sync(0xffffffffu, sum1, o);
        sum2 += __shfl_xor_sync(0xffffffffu, sum2, o);
    }
    float inv1 = 1.f / sum1, inv2 = 1.f / sum2;

    // ---- O = P V (un-normalized P; fold inv into epilogue) ----
    float o[4][4];
#pragma unroll
    for (int j = 0; j < 4; j++)
#pragma unroll
        for (int u = 0; u < 4; u++) o[j][u] = 0.f;

#pragma unroll
    for (int kt = 0; kt < 8; kt++) {
        uint32_t a[4];
        a[0] = pack_h2(s[2*kt][0],   s[2*kt][1]);
        a[1] = pack_h2(s[2*kt][2],   s[2*kt][3]);
        a[2] = pack_h2(s[2*kt+1][0], s[2*kt+1][1]);
        a[3] = pack_h2(s[2*kt+1][2], s[2*kt+1][3]);
#pragma unroll
        for (int j2 = 0; j2 < 2; j2++) {
            uint32_t b0[2], b1[2];
            LDSM4(b0[0], b0[1], b1[0], b1[1],
                  sVtu + (j2*16 + rb_in)*(VT_STR*2) + (kt*16 + gb_half*8)*2);
            MMA_F16(o[2*j2],   a, b0);
            MMA_F16(o[2*j2+1], a, b1);
        }
    }

    // ---- epilogue: write fp16 attention output ----
    int r1 = wid*16 + (lane >> 2);
    __half* op1 = g_attb + (size_t)(b*Lq + r1)*Dq + h*DKq + lc;
    __half* op2 = op1 + (size_t)8*Dq;
#pragma unroll
    for (int j = 0; j < 4; j++) {
        *reinterpret_cast<__half2*>(op1 + 8*j) = __floats2half2_rn(o[j][0]*inv1, o[j][1]*inv1);
        *reinterpret_cast<__half2*>(op2 + 8*j) = __floats2half2_rn(o[j][2]*inv2, o[j][3]*inv2);
    }
}

// ---------------- MoE router (one warp per token) --------------------------
__global__ __launch_bounds__(256)
void router_kernel(const float* __restrict__ rw, const float* __restrict__ rb, int layer)
{
    int warp = threadIdx.x >> 5, lane = threadIdx.x & 31;
    int t = (blockIdx.x << 3) + warp;

    float lg[Eq];
#pragma unroll
    for (int e = 0; e < Eq; e++) lg[e] = 0.f;
    const float* hp = g_h + (size_t)t*Dq;
    for (int kk = lane; kk < Dq; kk += 32) {
        float xv = hp[kk];
#pragma unroll
        for (int e = 0; e < Eq; e++) lg[e] += xv * rw[kk*Eq + e];
    }
#pragma unroll
    for (int e = 0; e < Eq; e++)
#pragma unroll
        for (int o = 16; o; o >>= 1) lg[e] += __shfl_xor_sync(0xffffffffu, lg[e], o);

    if (lane == 0) {
        float l[Eq], p[Eq];
        float mx = -1e30f;
#pragma unroll
        for (int e = 0; e < Eq; e++) { l[e] = lg[e] + rb[e]; mx = fmaxf(mx, l[e]); }
#pragma unroll
        for (int e = 0; e < Eq; e++) p[e] = __expf(l[e] - mx);
        int i0 = 0;
#pragma unroll
        for (int e = 1; e < Eq; e++) if (p[e] > p[i0]) i0 = e;
        int i1 = -1;
#pragma unroll
        for (int e = 0; e < Eq; e++) if (e != i0 && (i1 < 0 || p[e] > p[i1])) i1 = e;
        float w0 = p[i0], w1 = p[i1];
        float s2 = w0 + w1;
        w0 /= s2; w1 /= s2;

        int* cnt   = g_cnt  + layer*Eq;
        int* tokl  = g_tok  + (size_t)layer*Eq*NT;
        int* pairl = g_pair + (size_t)layer*Eq*NT;
        float* pwp = g_pw   + (size_t)layer*NP;
        int* pep   = g_pe   + (size_t)layer*NP;

        int p0 = atomicAdd(&cnt[i0], 1);
        tokl[i0*NT + p0] = t;  pairl[i0*NT + p0] = 2*t;
        int p1 = atomicAdd(&cnt[i1], 1);
        tokl[i1*NT + p1] = t;  pairl[i1*NT + p1] = 2*t + 1;
        pwp[2*t] = w0; pwp[2*t+1] = w1;
        pep[2*t] = i0; pep[2*t+1] = i1;
    }
}

// ---------------- MoE combine ----------------------------------------------
__global__ void moe_combine(const float* __restrict__ b2, int layer)
{
    int t = blockIdx.x, d = threadIdx.x;
    const float* pwp = g_pw + (size_t)layer*NP;
    const int*   pep = g_pe + (size_t)layer*NP;
    float w0 = pwp[2*t], w1 = pwp[2*t+1];
    int e0 = pep[2*t], e1 = pep[2*t+1];
    size_t i0 = (size_t)(2*t)*Dq + d;
    float nv = g_h[(size_t)t*Dq + d]
             + w0*(g_Y[i0]      + b2[e0*Dq + d])
             + w1*(g_Y[i0 + Dq] + b2[e1*Dq + d]);
    g_h [(size_t)t*Dq + d] = nv;
    g_hb[(size_t)t*Dq + d] = __float2half(nv);
}

// ---------------- final LN + prediction heads ------------------------------
__global__ __launch_bounds__(256)
void head_kernel(const float* __restrict__ lng, const float* __restrict__ lnb,
                 const float* __restrict__ pw,  const float* __restrict__ pb,
                 const float* __restrict__ uw,  const float* __restrict__ ub,
                 float* __restrict__ out)
{
    int b = blockIdx.x, tid = threadIdx.x;
    int warp = tid >> 5, lane = tid & 31;
    __shared__ float z[Dq];
    __shared__ float red[8];

    size_t t = (size_t)b*Lq + (Lq - 1);
    float v = g_h[t*Dq + tid];

    float s = v;
#pragma unroll
    for (int o = 16; o; o >>= 1) s += __shfl_xor_sync(0xffffffffu, s, o);
    if (lane == 0) red[warp] = s;
    __syncthreads();
    float tot = 0.f;
#pragma unroll
    for (int i = 0; i < 8; i++) tot += red[i];
    float mean = tot * (1.f / Dq);
    __syncthreads();

    float dv = v - mean;
    float q = dv * dv;
#pragma unroll
    for (int o = 16; o; o >>= 1) q += __shfl_xor_sync(0xffffffffu, q, o);
    if (lane == 0) red[warp] = q;
    __syncthreads();
    float vtot = 0.f;
#pragma unroll
    for (int i = 0; i < 8; i++) vtot += red[i];
    float var = vtot * (1.f / Dq);

    z[tid] = dv * rsqrtf(var + 1e-5f) * lng[tid] + lnb[tid];
    __syncthreads();

    for (int o = warp; o < 2*NHq; o += 8) {
        int j = o % NHq;
        int isu = o / NHq;
        const float* W = isu ? uw : pw;
        float p = 0.f;
        for (int d = lane; d < Dq; d += 32) p += z[d] * W[d*NHq + j];
#pragma unroll
        for (int off = 16; off; off >>= 1) p += __shfl_xor_sync(0xffffffffu, p, off);
        if (lane == 0) {
            float r = p + (isu ? ub[j] : pb[j]);
            if (isu) r = fmaxf(r, 0.f) + log1pf(__expf(-fabsf(r)));
            out[isu*(Bq*NHq) + b*NHq + j] = r;
        }
    }
}

// ---------------- host side -----------------------------------------------
extern "C" void kernel_launch(void* const* d_in, const int* in_sizes, int n_in,
                              void* d_out, int out_size)
{
    const float* x      = (const float*)d_in[0];
    const float* embw   = (const float*)d_in[1];
    const float* embb   = (const float*)d_in[2];
    const float* qw     = (const float*)d_in[3];
    const float* kw     = (const float*)d_in[4];
    const float* vw     = (const float*)d_in[5];
    const float* ow     = (const float*)d_in[6];
    const float* wfreq  = (const float*)d_in[7];
    const float* wphase = (const float*)d_in[8];
    const float* rw     = (const float*)d_in[9];
    const float* rb     = (const float*)d_in[10];
    const float* ew1    = (const float*)d_in[11];
    const float* eb1    = (const float*)d_in[12];
    const float* ew2    = (const float*)d_in[13];
    const float* eb2    = (const float*)d_in[14];
    const float* lng    = (const float*)d_in[15];
    const float* lnb    = (const float*)d_in[16];
    const float* predw  = (const float*)d_in[17];
    const float* predb  = (const float*)d_in[18];
    const float* uncw   = (const float*)d_in[19];
    const float* uncb   = (const float*)d_in[20];
    float* out = (float*)d_out;

    float *h, *Yb;
    __half *hb, *qkvh, *attb, *Hb, *wqkvt, *owtb, *w1tb, *w2tb;
    int *cnt, *tok, *pair;
    cudaGetSymbolAddress((void**)&h,     g_h);
    cudaGetSymbolAddress((void**)&hb,    g_hb);
    cudaGetSymbolAddress((void**)&qkvh,  g_qkvh);
    cudaGetSymbolAddress((void**)&attb,  g_attb);
    cudaGetSymbolAddress((void**)&Hb,    g_Hb);
    cudaGetSymbolAddress((void**)&Yb,    g_Y);
    cudaGetSymbolAddress((void**)&cnt,   g_cnt);
    cudaGetSymbolAddress((void**)&tok,   g_tok);
    cudaGetSymbolAddress((void**)&pair,  g_pair);
    cudaGetSymbolAddress((void**)&wqkvt, g_wqkvt);
    cudaGetSymbolAddress((void**)&owtb,  g_owtb);
    cudaGetSymbolAddress((void**)&w1tb,  g_w1tb);
    cudaGetSymbolAddress((void**)&w2tb,  g_w2tb);

    cudaFuncSetAttribute(hgemm, cudaFuncAttributeMaxDynamicSharedMemorySize, SMEM_BYTES);

    dim3 tb(32, 8);
    transpose_h16<<<dim3(8, 8, NLq), tb>>>(qw, wqkvt,          Dq, Dq, (size_t)NQKV*Dq);
    transpose_h16<<<dim3(8, 8, NLq), tb>>>(kw, wqkvt + 256*Dq, Dq, Dq, (size_t)NQKV*Dq);
    transpose_h16<<<dim3(8, 8, NLq), tb>>>(vw, wqkvt + 512*Dq, Dq, Dq, (size_t)NQKV*Dq);
    transpose_h16<<<dim3(8, 8, NLq), tb>>>(ow, owtb,           Dq, Dq, (size_t)Dq*Dq);
    transpose_h16<<<dim3(FFq/32, Dq/32, NMOEq*Eq), tb>>>(ew1, w1tb, Dq, FFq, (size_t)FFq*Dq);
    transpose_h16<<<dim3(Dq/32, FFq/32, NMOEq*Eq), tb>>>(ew2, w2tb, FFq, Dq, (size_t)Dq*FFq);

    zero_cnt_kernel<<<1, 32>>>();
    embed_kernel<<<NT, Dq>>>(x, embw, embb);

    for (int i = 0; i < NLq; i++) {
        // fused QKV projection -> fp16 qkvh [NT,768]
        hgemm<<<dim3(NT/128, NQKV/128, 1), 256, SMEM_BYTES>>>(
            hb, wqkvt + (size_t)i*NQKV*Dq, nullptr, qkvh, nullptr,
            NT, Dq, 0, NQKV, nullptr, nullptr, nullptr, 0, 0, 0, 3);

        attn_tc<<<Bq*Hq, 256>>>(wfreq + i*Hq, wphase + i*Hq);

        // O projection + residual (h fp32 + hb fp16)
        hgemm<<<dim3(NT/128, Dq/128, 1), 256, SMEM_BYTES>>>(
            attb, owtb + (size_t)i*Dq*Dq, h, hb, nullptr,
            NT, Dq, Dq, Dq, nullptr, nullptr, nullptr, 0, 0, 0, 1);

        if ((i & 1) == 0) {
            int j = i >> 1;
            router_kernel<<<NT/8, 256>>>(rw + (size_t)j*Dq*Eq, rb + j*Eq, j);

            hgemm<<<dim3(NT/128, FFq/128, Eq), 256, SMEM_BYTES>>>(
                hb, w1tb + (size_t)j*Eq*FFq*Dq, nullptr, Hb,
                eb1 + (size_t)j*Eq*FFq,
                0, Dq, 0, FFq,
                cnt + j*Eq, tok + (size_t)j*Eq*NT, pair + (size_t)j*Eq*NT,
                FFq*Dq, FFq, NT, 2);

            hgemm<<<dim3(NT/128, Dq/128, Eq), 256, SMEM_BYTES>>>(
                Hb, w2tb + (size_t)j*Eq*Dq*FFq, Yb, nullptr, nullptr,
                0, FFq, Dq, 0,
                cnt + j*Eq, pair + (size_t)j*Eq*NT, pair + (size_t)j*Eq*NT,
                Dq*FFq, 0, NT, 0);

            moe_combine<<<NT, Dq>>>(eb2 + (size_t)j*Eq*Dq, j);
        }
    }

    head_kernel<<<Bq, 256>>>(lng, lnb, predw, predb, uncw, uncb, out);
}

// round 6
// speedup vs baseline: 4.8070x; 1.0046x over previous
#include <cuda_runtime.h>
#include <cuda_fp16.h>
#include <math.h>
#include <stdint.h>

// Problem constants
#define Bq   256
#define Lq   128
#define INDq 6
#define Dq   256
#define Hq   8
#define DKq  32
#define NLq  6
#define Eq   8
#define FFq  1024
#define NMOEq 3
#define NHq  5
#define NT   (Bq*Lq)      // 32768 tokens
#define NP   (2*NT)       // 65536 token-expert pairs
#define NQKV 768

// ---------------- scratch (device globals; no allocation allowed) ----------
__device__ __align__(16) float  g_h   [NT*Dq];
__device__ __align__(16) __half g_hb  [NT*Dq];
__device__ __align__(16) __half g_qkvh[NT*NQKV];
__device__ __align__(16) __half g_attb[NT*Dq];
__device__ __align__(16) __half g_Hb  [NP*FFq];
__device__ int   g_cnt [NMOEq*Eq];
__device__ int   g_tok [NMOEq*Eq*NT];
__device__ int   g_pair[NMOEq*Eq*NT];
__device__ float g_pw  [NMOEq*NP];
// transposed fp16 weights, [N,K] K-major
__device__ __align__(16) __half g_wqkvt[NLq*NQKV*Dq];
__device__ __align__(16) __half g_owtb [NLq*Dq*Dq];
__device__ __align__(16) __half g_w1tb [NMOEq*Eq*FFq*Dq];
__device__ __align__(16) __half g_w2tb [NMOEq*Eq*Dq*FFq];

// ---------------- helpers ---------------------------------------------------
__device__ __forceinline__ uint32_t smem_u32(const void* p) {
    uint32_t a;
    asm("{ .reg .u64 t; cvta.to.shared.u64 t, %1; cvt.u32.u64 %0, t; }" : "=r"(a) : "l"(p));
    return a;
}
__device__ __forceinline__ void cp16(uint32_t saddr, const void* g, int sz) {
    asm volatile("cp.async.ca.shared.global [%0], [%1], 16, %2;"
                 :: "r"(saddr), "l"(g), "r"(sz) : "memory");
}
#define CP_COMMIT()  asm volatile("cp.async.commit_group;" ::: "memory")
#define CP_WAIT1()   asm volatile("cp.async.wait_group 1;" ::: "memory")

#define LDSM4(r0, r1, r2, r3, addr) \
    asm volatile("ldmatrix.sync.aligned.m8n8.x4.shared.b16 {%0,%1,%2,%3}, [%4];" \
                 : "=r"(r0), "=r"(r1), "=r"(r2), "=r"(r3) : "r"(addr))

#define MMA_F16(d, a, b) \
    asm volatile("mma.sync.aligned.m16n8k16.row.col.f32.f16.f16.f32 " \
                 "{%0,%1,%2,%3}, {%4,%5,%6,%7}, {%8,%9}, {%0,%1,%2,%3};" \
                 : "+f"((d)[0]), "+f"((d)[1]), "+f"((d)[2]), "+f"((d)[3]) \
                 : "r"((a)[0]), "r"((a)[1]), "r"((a)[2]), "r"((a)[3]), \
                   "r"((b)[0]), "r"((b)[1]))

__device__ __forceinline__ uint32_t pack_h2(float lo, float hi) {
    __half2 h = __floats2half2_rn(lo, hi);
    return *reinterpret_cast<uint32_t*>(&h);
}

// ---------------- small kernels -------------------------------------------
__global__ void zero_cnt_kernel() {
    if (threadIdx.x < NMOEq*Eq) g_cnt[threadIdx.x] = 0;
}

__global__ void embed_kernel(const float* __restrict__ x,
                             const float* __restrict__ w,
                             const float* __restrict__ b) {
    int t = blockIdx.x, d = threadIdx.x;
    float acc = b[d];
#pragma unroll
    for (int k = 0; k < INDq; k++) acc += x[t*INDq + k] * w[k*Dq + d];
    g_h [(size_t)t*Dq + d] = acc;
    g_hb[(size_t)t*Dq + d] = __float2half(acc);
}

__global__ void refresh_hb() {
    int i = blockIdx.x * 256 + threadIdx.x;
    float2 v = *reinterpret_cast<const float2*>(g_h + 2*(size_t)i);
    *reinterpret_cast<__half2*>(g_hb + 2*(size_t)i) = __floats2half2_rn(v.x, v.y);
}

// transpose to fp16: out[z*ostride + c*R + r] = h16(in[z][r][c])
__global__ void transpose_h16(const float* __restrict__ in, __half* __restrict__ out,
                              int R, int C, size_t ostride) {
    __shared__ float t[32][33];
    const float* ip = in + (size_t)blockIdx.z * R * C;
    __half* op = out + (size_t)blockIdx.z * ostride;
    int c0 = blockIdx.x * 32, r0 = blockIdx.y * 32;
    int tx = threadIdx.x, ty = threadIdx.y;
#pragma unroll
    for (int j = 0; j < 32; j += 8)
        t[ty + j][tx] = ip[(size_t)(r0 + ty + j) * C + c0 + tx];
    __syncthreads();
#pragma unroll
    for (int j = 0; j < 32; j += 8)
        op[(size_t)(c0 + ty + j) * R + r0 + tx] = __float2half(t[tx][ty + j]);
}

// ---------------- fp16 warp-MMA GEMM (128x128 tile, BK=64, 3-stage) --------
// epi: 0 = fp32 C; 1 = residual add C + fp16 Cb; 2 = gelu(acc+bias)->Cb;
//      3 = plain fp16 Cb; 4 = moe-down: atomicAdd(C[t], w*(acc+bias[e]))
#define STG   32768              // bytes per stage (A 16KB + B 16KB)
#define SMEM_BYTES (3*STG)       // 96KB

__global__ __launch_bounds__(256, 2)
void hgemm(const __half* __restrict__ A,
           const __half* __restrict__ Btbase,
           float* __restrict__ C,
           __half* __restrict__ Cb,
           const float* __restrict__ biasbase,
           const float* __restrict__ pwbase,
           int M, int K, int ldc, int ldcb,
           const int* __restrict__ cntp,
           const int* __restrict__ aidxb,
           const int* __restrict__ cidxb,
           int zBstride, int zbstride, int idxcap, int epi)
{
    extern __shared__ char sm[];
    int e = blockIdx.z;
    int Mloc = cntp ? cntp[e] : M;
    int m0 = blockIdx.x << 7;
    if (m0 >= Mloc) return;
    int n0 = blockIdx.y << 7;
    const __half* Bp = Btbase + (size_t)e * zBstride;
    const int* al = aidxb ? aidxb + (size_t)e * idxcap : nullptr;
    const int* cl = cidxb ? cidxb + (size_t)e * idxcap : nullptr;

    int tid = threadIdx.x, wid = tid >> 5, lane = tid & 31;
    int warp_m = wid & 1, warp_n = wid >> 1;
    uint32_t su = smem_u32(sm);

    int gld = tid & 7;
    int srow0 = tid >> 3;

    int rowA[4], szA[4];
    uint32_t sw[4];
#pragma unroll
    for (int i = 0; i < 4; i++) {
        int r = srow0 + 32*i;
        int gm = m0 + r;
        bool v = gm < Mloc;
        rowA[i] = v ? (al ? al[gm] : gm) : 0;
        szA[i] = v ? 16 : 0;
        sw[i] = (uint32_t)(r*128 + ((gld ^ (r & 7)) << 4));
    }

    float d[4][4][4];
#pragma unroll
    for (int i = 0; i < 4; i++)
#pragma unroll
        for (int j = 0; j < 4; j++)
#pragma unroll
            for (int u = 0; u < 4; u++) d[i][j][u] = 0.f;

#define ISSUE(chunk, slot) do { \
    int kt = (chunk) << 6; \
    uint32_t base = su + (uint32_t)(slot)*STG; \
    _Pragma("unroll") \
    for (int i = 0; i < 4; i++) { \
        int r = srow0 + 32*i; \
        cp16(base + sw[i], A + (size_t)rowA[i]*K + kt + gld*8, szA[i]); \
        cp16(base + 16384 + sw[i], Bp + (size_t)(n0 + r)*K + kt + gld*8, 16); \
    } \
} while (0)

    int nch = K >> 6;
    ISSUE(0, 0); CP_COMMIT();
    ISSUE(1, 1); CP_COMMIT();

    int ra = (lane & 15);
    int ga_half = lane >> 4;
    int rb_in = ((lane >> 4) << 3) + (lane & 7);
    int gb_half = (lane >> 3) & 1;

    int slot = 0;
    for (int c = 0; c < nch; c++) {
        CP_WAIT1();
        __syncthreads();          // stage c ready; slot (c+2)%3 free for reuse
        if (c + 2 < nch) {
            int ns = slot + 2; if (ns >= 3) ns -= 3;
            ISSUE(c + 2, ns);
        }
        CP_COMMIT();
        uint32_t Ab = su + (uint32_t)slot*STG;
        uint32_t Bb = Ab + 16384;
#pragma unroll
        for (int ks = 0; ks < 4; ks++) {
            uint32_t a[4][4], b[4][2];
#pragma unroll
            for (int i = 0; i < 4; i++) {
                int r = warp_m*64 + i*16 + ra;
                int g = ks*2 + ga_half;
                LDSM4(a[i][0], a[i][1], a[i][2], a[i][3],
                      Ab + r*128 + ((g ^ (r & 7)) << 4));
            }
#pragma unroll
            for (int j2 = 0; j2 < 2; j2++) {
                int r = warp_n*32 + j2*16 + rb_in;
                int g = ks*2 + gb_half;
                LDSM4(b[2*j2][0], b[2*j2][1], b[2*j2+1][0], b[2*j2+1][1],
                      Bb + r*128 + ((g ^ (r & 7)) << 4));
            }
#pragma unroll
            for (int i = 0; i < 4; i++)
#pragma unroll
                for (int j = 0; j < 4; j++)
                    MMA_F16(d[i][j], a[i], b[j]);
        }
        if (++slot == 3) slot = 0;
    }

    const float* bi = (epi >= 2) ? (biasbase + (size_t)e*zbstride) : nullptr;
#pragma unroll
    for (int i = 0; i < 4; i++) {
        int rl = warp_m*64 + i*16 + (lane >> 2);
#pragma unroll
        for (int half = 0; half < 2; half++) {
            int gm = m0 + rl + half*8;
            if (gm >= Mloc) continue;
            int cr = cl ? cl[gm] : gm;
#pragma unroll
            for (int j = 0; j < 4; j++) {
                int gcol = n0 + warp_n*32 + j*8 + 2*(lane & 3);
                float v0 = d[i][j][half*2 + 0];
                float v1 = d[i][j][half*2 + 1];
                if (epi == 0) {
                    *reinterpret_cast<float2*>(C + (size_t)cr*ldc + gcol) = make_float2(v0, v1);
                } else if (epi == 1) {
                    float* cp = C + (size_t)cr*ldc + gcol;
                    float2 o = *reinterpret_cast<float2*>(cp);
                    o.x += v0; o.y += v1;
                    *reinterpret_cast<float2*>(cp) = o;
                    *reinterpret_cast<__half2*>(Cb + (size_t)cr*ldcb + gcol) =
                        __floats2half2_rn(o.x, o.y);
                } else if (epi == 2) {
                    float x0 = v0 + bi[gcol];
                    float x1 = v1 + bi[gcol + 1];
                    x0 = 0.5f * x0 * (1.0f + erff(x0 * 0.70710678118654752f));
                    x1 = 0.5f * x1 * (1.0f + erff(x1 * 0.70710678118654752f));
                    *reinterpret_cast<__half2*>(Cb + (size_t)cr*ldcb + gcol) =
                        __floats2half2_rn(x0, x1);
                } else if (epi == 3) {
                    *reinterpret_cast<__half2*>(Cb + (size_t)cr*ldcb + gcol) =
                        __floats2half2_rn(v0, v1);
                } else {
                    // moe-down: cr = pair id; token = cr>>1; weighted atomic add
                    int t = cr >> 1;
                    float w = pwbase[cr];
                    float* cp = C + (size_t)t*ldc + gcol;
                    atomicAdd(cp,     w * (v0 + bi[gcol]));
                    atomicAdd(cp + 1, w * (v1 + bi[gcol + 1]));
                }
            }
        }
    }
}

// ---------------- tensor-core attention ------------------------------------
#define QK_STR 40
#define VT_STR 136

__global__ __launch_bounds__(256)
void attn_tc(const float* __restrict__ wfreq, const float* __restrict__ wphase)
{
    __shared__ __half sQ[128*QK_STR];
    __shared__ __half sK[128*QK_STR];
    __shared__ __half sVt[32*VT_STR];
    __shared__ float  wv[Lq];

    int b = blockIdx.x >> 3, h = blockIdx.x & 7;
    int tid = threadIdx.x, wid = tid >> 5, lane = tid & 31;
    const __half* src = g_qkvh + (size_t)(b*Lq)*NQKV + h*DKq;

#pragma unroll
    for (int it = 0; it < 2; it++) {
        int i = tid + (it << 8);
        int r = i >> 2, g = i & 3;
        const __half* rp = src + (size_t)r*NQKV;
        *reinterpret_cast<uint4*>(&sQ[r*QK_STR + g*8]) =
            *reinterpret_cast<const uint4*>(rp + g*8);
        *reinterpret_cast<uint4*>(&sK[r*QK_STR + g*8]) =
            *reinterpret_cast<const uint4*>(rp + 256 + g*8);
        uint4 vv = *reinterpret_cast<const uint4*>(rp + 512 + g*8);
        const __half* vh = reinterpret_cast<const __half*>(&vv);
#pragma unroll
        for (int u = 0; u < 8; u++)
            sVt[(g*8 + u)*VT_STR + r] = vh[u];
    }
    if (tid < Lq) {
        float f = wfreq[h], ph = wphase[h];
        wv[tid] = cosf((6.2831853071795864f * f) * (float)tid + ph) * 0.17677669529663687f;
    }
    __syncthreads();

    uint32_t sQu = smem_u32(sQ), sKu = smem_u32(sK), sVtu = smem_u32(sVt);
    int rb_in = ((lane >> 4) << 3) + (lane & 7);
    int gb_half = (lane >> 3) & 1;

    float s[16][4];
#pragma unroll
    for (int j = 0; j < 16; j++)
#pragma unroll
        for (int u = 0; u < 4; u++) s[j][u] = 0.f;

#pragma unroll
    for (int ks = 0; ks < 2; ks++) {
        uint32_t a[4];
        LDSM4(a[0], a[1], a[2], a[3],
              sQu + (wid*16 + (lane & 15))*(QK_STR*2) + (ks*16 + (lane >> 4)*8)*2);
#pragma unroll
        for (int j2 = 0; j2 < 8; j2++) {
            uint32_t b0[2], b1[2];
            LDSM4(b0[0], b0[1], b1[0], b1[1],
                  sKu + (j2*16 + rb_in)*(QK_STR*2) + (ks*16 + gb_half*8)*2);
            MMA_F16(s[2*j2],   a, b0);
            MMA_F16(s[2*j2+1], a, b1);
        }
    }

    int lc = 2*(lane & 3);
    float m1 = -1e30f, m2 = -1e30f;
#pragma unroll
    for (int j = 0; j < 16; j++) {
        float w0 = wv[8*j + lc], w1 = wv[8*j + lc + 1];
        s[j][0] *= w0; s[j][1] *= w1; s[j][2] *= w0; s[j][3] *= w1;
        m1 = fmaxf(m1, fmaxf(s[j][0], s[j][1]));
        m2 = fmaxf(m2, fmaxf(s[j][2], s[j][3]));
    }
#pragma unroll
    for (int o = 1; o <= 2; o <<= 1) {
        m1 = fmaxf(m1, __shfl_xor_sync(0xffffffffu, m1, o));
        m2 = fmaxf(m2, __shfl_xor_sync(0xffffffffu, m2, o));
    }
    float sum1 = 0.f, sum2 = 0.f;
#pragma unroll
    for (int j = 0; j < 16; j++) {
        s[j][0] = __expf(s[j][0] - m1); s[j][1] = __expf(s[j][1] - m1);
        s[j][2] = __expf(s[j][2] - m2); s[j][3] = __expf(s[j][3] - m2);
        sum1 += s[j][0] + s[j][1];
        sum2 += s[j][2] + s[j][3];
    }
#pragma unroll
    for (int o = 1; o <= 2; o <<= 1) {
        sum1 += __shfl_xor_sync(0xffffffffu, sum1, o);
        sum2 += __shfl_xor_sync(0xffffffffu, sum2, o);
    }
    float inv1 = 1.f / sum1, inv2 = 1.f / sum2;

    float o[4][4];
#pragma unroll
    for (int j = 0; j < 4; j++)
#pragma unroll
        for (int u = 0; u < 4; u++) o[j][u] = 0.f;

#pragma unroll
    for (int kt = 0; kt < 8; kt++) {
        uint32_t a[4];
        a[0] = pack_h2(s[2*kt][0],   s[2*kt][1]);
        a[1] = pack_h2(s[2*kt][2],   s[2*kt][3]);
        a[2] = pack_h2(s[2*kt+1][0], s[2*kt+1][1]);
        a[3] = pack_h2(s[2*kt+1][2], s[2*kt+1][3]);
#pragma unroll
        for (int j2 = 0; j2 < 2; j2++) {
            uint32_t b0[2], b1[2];
            LDSM4(b0[0], b0[1], b1[0], b1[1],
                  sVtu + (j2*16 + rb_in)*(VT_STR*2) + (kt*16 + gb_half*8)*2);
            MMA_F16(o[2*j2],   a, b0);
            MMA_F16(o[2*j2+1], a, b1);
        }
    }

    int r1 = wid*16 + (lane >> 2);
    __half* op1 = g_attb + (size_t)(b*Lq + r1)*Dq + h*DKq + lc;
    __half* op2 = op1 + (size_t)8*Dq;
#pragma unroll
    for (int j = 0; j < 4; j++) {
        *reinterpret_cast<__half2*>(op1 + 8*j) = __floats2half2_rn(o[j][0]*inv1, o[j][1]*inv1);
        *reinterpret_cast<__half2*>(op2 + 8*j) = __floats2half2_rn(o[j][2]*inv2, o[j][3]*inv2);
    }
}

// ---------------- MoE router (one warp per token) --------------------------
__global__ __launch_bounds__(256)
void router_kernel(const float* __restrict__ rw, const float* __restrict__ rb, int layer)
{
    int warp = threadIdx.x >> 5, lane = threadIdx.x & 31;
    int t = (blockIdx.x << 3) + warp;

    float lg[Eq];
#pragma unroll
    for (int e = 0; e < Eq; e++) lg[e] = 0.f;
    const float* hp = g_h + (size_t)t*Dq;
    for (int kk = lane; kk < Dq; kk += 32) {
        float xv = hp[kk];
#pragma unroll
        for (int e = 0; e < Eq; e++) lg[e] += xv * rw[kk*Eq + e];
    }
#pragma unroll
    for (int e = 0; e < Eq; e++)
#pragma unroll
        for (int o = 16; o; o >>= 1) lg[e] += __shfl_xor_sync(0xffffffffu, lg[e], o);

    if (lane == 0) {
        float l[Eq], p[Eq];
        float mx = -1e30f;
#pragma unroll
        for (int e = 0; e < Eq; e++) { l[e] = lg[e] + rb[e]; mx = fmaxf(mx, l[e]); }
#pragma unroll
        for (int e = 0; e < Eq; e++) p[e] = __expf(l[e] - mx);
        int i0 = 0;
#pragma unroll
        for (int e = 1; e < Eq; e++) if (p[e] > p[i0]) i0 = e;
        int i1 = -1;
#pragma unroll
        for (int e = 0; e < Eq; e++) if (e != i0 && (i1 < 0 || p[e] > p[i1])) i1 = e;
        float w0 = p[i0], w1 = p[i1];
        float s2 = w0 + w1;
        w0 /= s2; w1 /= s2;

        int* cnt   = g_cnt  + layer*Eq;
        int* tokl  = g_tok  + (size_t)layer*Eq*NT;
        int* pairl = g_pair + (size_t)layer*Eq*NT;
        float* pwp = g_pw   + (size_t)layer*NP;

        int p0 = atomicAdd(&cnt[i0], 1);
        tokl[i0*NT + p0] = t;  pairl[i0*NT + p0] = 2*t;
        int p1 = atomicAdd(&cnt[i1], 1);
        tokl[i1*NT + p1] = t;  pairl[i1*NT + p1] = 2*t + 1;
        pwp[2*t] = w0; pwp[2*t+1] = w1;
    }
}

// ---------------- final LN + prediction heads ------------------------------
__global__ __launch_bounds__(256)
void head_kernel(const float* __restrict__ lng, const float* __restrict__ lnb,
                 const float* __restrict__ pw,  const float* __restrict__ pb,
                 const float* __restrict__ uw,  const float* __restrict__ ub,
                 float* __restrict__ out)
{
    int b = blockIdx.x, tid = threadIdx.x;
    int warp = tid >> 5, lane = tid & 31;
    __shared__ float z[Dq];
    __shared__ float red[8];

    size_t t = (size_t)b*Lq + (Lq - 1);
    float v = g_h[t*Dq + tid];

    float s = v;
#pragma unroll
    for (int o = 16; o; o >>= 1) s += __shfl_xor_sync(0xffffffffu, s, o);
    if (lane == 0) red[warp] = s;
    __syncthreads();
    float tot = 0.f;
#pragma unroll
    for (int i = 0; i < 8; i++) tot += red[i];
    float mean = tot * (1.f / Dq);
    __syncthreads();

    float dv = v - mean;
    float q = dv * dv;
#pragma unroll
    for (int o = 16; o; o >>= 1) q += __shfl_xor_sync(0xffffffffu, q, o);
    if (lane == 0) red[warp] = q;
    __syncthreads();
    float vtot = 0.f;
#pragma unroll
    for (int i = 0; i < 8; i++) vtot += red[i];
    float var = vtot * (1.f / Dq);

    z[tid] = dv * rsqrtf(var + 1e-5f) * lng[tid] + lnb[tid];
    __syncthreads();

    for (int o = warp; o < 2*NHq; o += 8) {
        int j = o % NHq;
        int isu = o / NHq;
        const float* W = isu ? uw : pw;
        float p = 0.f;
        for (int d = lane; d < Dq; d += 32) p += z[d] * W[d*NHq + j];
#pragma unroll
        for (int off = 16; off; off >>= 1) p += __shfl_xor_sync(0xffffffffu, p, off);
        if (lane == 0) {
            float r = p + (isu ? ub[j] : pb[j]);
            if (isu) r = fmaxf(r, 0.f) + log1pf(__expf(-fabsf(r)));
            out[isu*(Bq*NHq) + b*NHq + j] = r;
        }
    }
}

// ---------------- host side -----------------------------------------------
extern "C" void kernel_launch(void* const* d_in, const int* in_sizes, int n_in,
                              void* d_out, int out_size)
{
    const float* x      = (const float*)d_in[0];
    const float* embw   = (const float*)d_in[1];
    const float* embb   = (const float*)d_in[2];
    const float* qw     = (const float*)d_in[3];
    const float* kw     = (const float*)d_in[4];
    const float* vw     = (const float*)d_in[5];
    const float* ow     = (const float*)d_in[6];
    const float* wfreq  = (const float*)d_in[7];
    const float* wphase = (const float*)d_in[8];
    const float* rw     = (const float*)d_in[9];
    const float* rb     = (const float*)d_in[10];
    const float* ew1    = (const float*)d_in[11];
    const float* eb1    = (const float*)d_in[12];
    const float* ew2    = (const float*)d_in[13];
    const float* eb2    = (const float*)d_in[14];
    const float* lng    = (const float*)d_in[15];
    const float* lnb    = (const float*)d_in[16];
    const float* predw  = (const float*)d_in[17];
    const float* predb  = (const float*)d_in[18];
    const float* uncw   = (const float*)d_in[19];
    const float* uncb   = (const float*)d_in[20];
    float* out = (float*)d_out;

    float *h, *pw_;
    __half *hb, *qkvh, *attb, *Hb, *wqkvt, *owtb, *w1tb, *w2tb;
    int *cnt, *tok, *pair;
    cudaGetSymbolAddress((void**)&h,     g_h);
    cudaGetSymbolAddress((void**)&hb,    g_hb);
    cudaGetSymbolAddress((void**)&qkvh,  g_qkvh);
    cudaGetSymbolAddress((void**)&attb,  g_attb);
    cudaGetSymbolAddress((void**)&Hb,    g_Hb);
    cudaGetSymbolAddress((void**)&cnt,   g_cnt);
    cudaGetSymbolAddress((void**)&tok,   g_tok);
    cudaGetSymbolAddress((void**)&pair,  g_pair);
    cudaGetSymbolAddress((void**)&pw_,   g_pw);
    cudaGetSymbolAddress((void**)&wqkvt, g_wqkvt);
    cudaGetSymbolAddress((void**)&owtb,  g_owtb);
    cudaGetSymbolAddress((void**)&w1tb,  g_w1tb);
    cudaGetSymbolAddress((void**)&w2tb,  g_w2tb);

    cudaFuncSetAttribute(hgemm, cudaFuncAttributeMaxDynamicSharedMemorySize, SMEM_BYTES);

    dim3 tb(32, 8);
    transpose_h16<<<dim3(8, 8, NLq), tb>>>(qw, wqkvt,          Dq, Dq, (size_t)NQKV*Dq);
    transpose_h16<<<dim3(8, 8, NLq), tb>>>(kw, wqkvt + 256*Dq, Dq, Dq, (size_t)NQKV*Dq);
    transpose_h16<<<dim3(8, 8, NLq), tb>>>(vw, wqkvt + 512*Dq, Dq, Dq, (size_t)NQKV*Dq);
    transpose_h16<<<dim3(8, 8, NLq), tb>>>(ow, owtb,           Dq, Dq, (size_t)Dq*Dq);
    transpose_h16<<<dim3(FFq/32, Dq/32, NMOEq*Eq), tb>>>(ew1, w1tb, Dq, FFq, (size_t)FFq*Dq);
    transpose_h16<<<dim3(Dq/32, FFq/32, NMOEq*Eq), tb>>>(ew2, w2tb, FFq, Dq, (size_t)Dq*FFq);

    zero_cnt_kernel<<<1, 32>>>();
    embed_kernel<<<NT, Dq>>>(x, embw, embb);

    for (int i = 0; i < NLq; i++) {
        hgemm<<<dim3(NT/128, NQKV/128, 1), 256, SMEM_BYTES>>>(
            hb, wqkvt + (size_t)i*NQKV*Dq, nullptr, qkvh, nullptr, nullptr,
            NT, Dq, 0, NQKV, nullptr, nullptr, nullptr, 0, 0, 0, 3);

        attn_tc<<<Bq*Hq, 256>>>(wfreq + i*Hq, wphase + i*Hq);

        hgemm<<<dim3(NT/128, Dq/128, 1), 256, SMEM_BYTES>>>(
            attb, owtb + (size_t)i*Dq*Dq, h, hb, nullptr, nullptr,
            NT, Dq, Dq, Dq, nullptr, nullptr, nullptr, 0, 0, 0, 1);

        if ((i & 1) == 0) {
            int j = i >> 1;
            router_kernel<<<NT/8, 256>>>(rw + (size_t)j*Dq*Eq, rb + j*Eq, j);

            hgemm<<<dim3(NT/128, FFq/128, Eq), 256, SMEM_BYTES>>>(
                hb, w1tb + (size_t)j*Eq*FFq*Dq, nullptr, Hb,
                eb1 + (size_t)j*Eq*FFq, nullptr,
                0, Dq, 0, FFq,
                cnt + j*Eq, tok + (size_t)j*Eq*NT, pair + (size_t)j*Eq*NT,
                FFq*Dq, FFq, NT, 2);

            // down-proj fused with combine: atomicAdd w*(acc + b2[e]) into h
            hgemm<<<dim3(NT/128, Dq/128, Eq), 256, SMEM_BYTES>>>(
                Hb, w2tb + (size_t)j*Eq*Dq*FFq, h, nullptr,
                eb2 + (size_t)j*Eq*Dq, pw_ + (size_t)j*NP,
                0, FFq, Dq, 0,
                cnt + j*Eq, pair + (size_t)j*Eq*NT, pair + (size_t)j*Eq*NT,
                Dq*FFq, Dq, NT, 4);

            refresh_hb<<<NT*Dq/512, 256>>>();
        }
    }

    head_kernel<<<Bq, 256>>>(lng, lnb, predw, predb, uncw, uncb, out);
}